// round 1
// baseline (speedup 1.0000x reference)
#include <cuda_runtime.h>
#include <math.h>

// Problem constants (fixed shapes)
#define NTOK 8192          // N = B*T = 4*2048
#define DM   768           // D
#define NE   8             // experts
#define NKA  16384         // N*K
#define HF   2048          // H_FF
#define CAPC 4096          // capacity C
#define MROW 24576         // N*L, L=3
#define QKVW 2304          // 3*D

// ---------------- scratch (device globals; no allocations) ----------------
__device__ float g_router_sum[NE];
__device__ float g_assign_sum[NE];
__device__ float g_z2;
__device__ int   g_counts[NE];
__device__ int   g_fill[NE];
__device__ int   g_offsets[NE];
__device__ int   g_keepcnt;
__device__ int   g_te[NKA];
__device__ float g_prio[NKA];
__device__ float g_tpk[NKA];
__device__ float g_keep[NKA];
__device__ int   g_idx_list[NKA];
__device__ int   g_tile_e[272];
__device__ int   g_tile_r0[272];
__device__ int   g_tile_rows[272];
__device__ int   g_ntiles;

__device__ float g_act[(size_t)(NKA + 64) * HF];
__device__ float g_tokens[(size_t)MROW * DM];
__device__ float g_qkv[(size_t)MROW * QKVW];
__device__ float g_attn[(size_t)MROW * DM];
__device__ float g_u[(size_t)MROW * DM];
__device__ float g_hbuf[(size_t)MROW * DM];
__device__ float g_fm[(size_t)NTOK * DM];
__device__ float g_w2t[(size_t)NE * HF * DM];

// ---------------- small utility kernels ----------------
__global__ void zero_accum_kernel() {
    int t = threadIdx.x;
    if (t < NE) { g_router_sum[t] = 0.f; g_assign_sum[t] = 0.f; g_counts[t] = 0; g_fill[t] = 0; }
    if (t == 0) { g_z2 = 0.f; g_keepcnt = 0; }
}

__global__ void w2t_kernel(const float* __restrict__ w2) {
    // w2: (E, D, H) -> g_w2t: (E, H, D)
    size_t total = (size_t)NE * HF * DM;
    for (size_t i = blockIdx.x * blockDim.x + threadIdx.x; i < total; i += (size_t)gridDim.x * blockDim.x) {
        size_t e = i / ((size_t)HF * DM);
        size_t rem = i - e * (size_t)HF * DM;
        size_t h = rem / DM;
        size_t d = rem - h * DM;
        g_w2t[i] = w2[e * (size_t)DM * HF + d * HF + h];
    }
}

__global__ void med_init_kernel(const float* __restrict__ mediator) {
    size_t total = (size_t)NTOK * DM;
    for (size_t i = blockIdx.x * blockDim.x + threadIdx.x; i < total; i += (size_t)gridDim.x * blockDim.x) {
        size_t n = i / DM;
        size_t d = i - n * DM;
        g_tokens[(n * 3 + 2) * DM + d] = mediator[d];
    }
}

// ---------------- gate + top-k + stats ----------------
__global__ void gate_kernel(const float* __restrict__ x, const float* __restrict__ gw,
                            float* __restrict__ out) {
    __shared__ float xs[DM];
    __shared__ float lg[NE];
    int n = blockIdx.x, tid = threadIdx.x;
    for (int i = tid; i < DM; i += 256) xs[i] = x[(size_t)n * DM + i];
    __syncthreads();
    int w = tid >> 5, lane = tid & 31;
    const float* g = gw + (size_t)w * DM;
    float s = 0.f;
    for (int i = lane; i < DM; i += 32) s += xs[i] * g[i];
    #pragma unroll
    for (int o = 16; o; o >>= 1) s += __shfl_xor_sync(0xffffffffu, s, o);
    if (lane == 0) lg[w] = s;
    __syncthreads();
    if (tid == 0) {
        float l[NE];
        #pragma unroll
        for (int e = 0; e < NE; e++) l[e] = lg[e];
        int i1 = 0; float v1 = l[0];
        for (int e = 1; e < NE; e++) if (l[e] > v1) { v1 = l[e]; i1 = e; }
        int i2 = -1; float v2 = -3.4e38f;
        for (int e = 0; e < NE; e++) if (e != i1 && l[e] > v2) { v2 = l[e]; i2 = e; }
        float e2 = expf(v2 - v1);
        float inv = 1.f / (1.f + e2);
        float p1 = inv, p2 = e2 * inv;
        float se = 0.f;
        for (int e = 0; e < NE; e++) se += expf(l[e] - v1);
        float z = v1 + logf(se);
        for (int e = 0; e < NE; e++) atomicAdd(&g_router_sum[e], expf(l[e] - v1) / se);
        atomicAdd(&g_assign_sum[i1], p1);
        atomicAdd(&g_assign_sum[i2], p2);
        atomicAdd(&g_z2, z * z);
        atomicAdd(&g_counts[i1], 1);
        atomicAdd(&g_counts[i2], 1);
        g_te[2 * n] = i1; g_te[2 * n + 1] = i2;
        g_prio[2 * n] = v1; g_prio[2 * n + 1] = v2;
        g_tpk[2 * n] = p1; g_tpk[2 * n + 1] = p2;
        out[(size_t)NTOK * DM + 1 + 2 * n]     = (float)i1;
        out[(size_t)NTOK * DM + 1 + 2 * n + 1] = (float)i2;
    }
}

// ---------------- tile builder / scatter / keep ----------------
__global__ void build_tiles_kernel() {
    if (threadIdx.x != 0 || blockIdx.x != 0) return;
    int off = 0, nt = 0;
    for (int e = 0; e < NE; e++) {
        g_offsets[e] = off;
        int c = g_counts[e];
        int ntile = (c + 63) >> 6;
        for (int t = 0; t < ntile; t++) {
            g_tile_e[nt] = e;
            g_tile_r0[nt] = off + t * 64;
            int r = c - t * 64;
            g_tile_rows[nt] = r < 64 ? r : 64;
            nt++;
        }
        off += c;
    }
    g_ntiles = nt;
}

__global__ void scatter_kernel() {
    int i = blockIdx.x * 256 + threadIdx.x;
    if (i >= NKA) return;
    int e = g_te[i];
    int p = atomicAdd(&g_fill[e], 1);
    g_idx_list[g_offsets[e] + p] = i;
}

__global__ void keep_kernel() {
    int i = blockIdx.x * 256 + threadIdx.x;
    if (i >= NKA) return;
    int e = g_te[i];
    int kp;
    if (g_counts[e] <= CAPC) {
        kp = 1;
    } else {
        float pi = g_prio[i];
        int rank = 0;
        for (int j = 0; j < NKA; j++) {
            if (g_te[j] == e) {
                float pj = g_prio[j];
                if (pj > pi || (pj == pi && j < i)) rank++;
            }
        }
        kp = (rank < CAPC) ? 1 : 0;
    }
    g_keep[i] = (float)kp;
    atomicAdd(&g_keepcnt, kp);
}

// ---------------- expert FFN pass A: act = silu(2x@Wg^T)*(2x@Wu^T) ----------------
__global__ void expertA_kernel(const float* __restrict__ x, const float* __restrict__ w13) {
    int t = blockIdx.x;
    if (t >= g_ntiles) return;
    int e = g_tile_e[t], r0 = g_tile_r0[t], rows = g_tile_rows[t];
    int h0 = blockIdx.y * 64;
    __shared__ float As[16][64];
    __shared__ float Bg[16][64];
    __shared__ float Bu[16][64];
    __shared__ int tok[64];
    int tid = threadIdx.x;
    if (tid < 64) tok[tid] = (tid < rows) ? (g_idx_list[r0 + tid] >> 1) : 0;
    __syncthreads();
    int lrow = tid >> 2, lk4 = (tid & 3) << 2;
    int tx = tid & 15, ty = tid >> 4;
    const float* wg = w13 + (size_t)e * 2 * HF * DM + (size_t)h0 * DM + (size_t)lrow * DM + lk4;
    const float* wu = wg + (size_t)HF * DM;
    const float* xp = x + (size_t)tok[lrow] * DM + lk4;
    float ag[4][4], au[4][4];
    #pragma unroll
    for (int i = 0; i < 4; i++)
        #pragma unroll
        for (int j = 0; j < 4; j++) { ag[i][j] = 0.f; au[i][j] = 0.f; }
    for (int kk = 0; kk < DM; kk += 16) {
        float4 a4 = *(const float4*)(xp + kk);
        float4 g4 = *(const float4*)(wg + kk);
        float4 u4 = *(const float4*)(wu + kk);
        As[lk4 + 0][lrow] = 2.f * a4.x; As[lk4 + 1][lrow] = 2.f * a4.y;
        As[lk4 + 2][lrow] = 2.f * a4.z; As[lk4 + 3][lrow] = 2.f * a4.w;
        Bg[lk4 + 0][lrow] = g4.x; Bg[lk4 + 1][lrow] = g4.y;
        Bg[lk4 + 2][lrow] = g4.z; Bg[lk4 + 3][lrow] = g4.w;
        Bu[lk4 + 0][lrow] = u4.x; Bu[lk4 + 1][lrow] = u4.y;
        Bu[lk4 + 2][lrow] = u4.z; Bu[lk4 + 3][lrow] = u4.w;
        __syncthreads();
        #pragma unroll
        for (int k = 0; k < 16; k++) {
            float a[4], bg[4], bu[4];
            #pragma unroll
            for (int i = 0; i < 4; i++) a[i] = As[k][ty * 4 + i];
            #pragma unroll
            for (int j = 0; j < 4; j++) { bg[j] = Bg[k][tx * 4 + j]; bu[j] = Bu[k][tx * 4 + j]; }
            #pragma unroll
            for (int i = 0; i < 4; i++)
                #pragma unroll
                for (int j = 0; j < 4; j++) { ag[i][j] += a[i] * bg[j]; au[i][j] += a[i] * bu[j]; }
        }
        __syncthreads();
    }
    #pragma unroll
    for (int i = 0; i < 4; i++) {
        int r = ty * 4 + i;
        if (r < rows) {
            float* ap = g_act + (size_t)(r0 + r) * HF + h0;
            #pragma unroll
            for (int j = 0; j < 4; j++) {
                float gv = ag[i][j];
                float sv = gv / (1.f + expf(-gv));
                ap[tx * 4 + j] = sv * au[i][j];
            }
        }
    }
}

// ---------------- expert FFN pass B: y = keep*(x + act@W2^T) -> tokens slots ----------------
__global__ void expertB_kernel(const float* __restrict__ x) {
    int t = blockIdx.x;
    if (t >= g_ntiles) return;
    int e = g_tile_e[t], r0 = g_tile_r0[t], rows = g_tile_rows[t];
    int d0 = blockIdx.y * 64;
    __shared__ float As[16][64];
    __shared__ float Bs[16][64];
    int tid = threadIdx.x;
    int lrow = tid >> 2, lk4 = (tid & 3) << 2;
    int tx = tid & 15, ty = tid >> 4;
    const float* ap = g_act + (size_t)(r0 + lrow) * HF + lk4;
    const float* wp = g_w2t + (size_t)e * HF * DM + (size_t)(d0 + lrow) * 1;
    // B tile: Bs[k][d] = w2t[e][kk+k][d0+d]; load by (lrow=d index? ) -> use lrow as d, lk4 as k
    const float* wbase = g_w2t + (size_t)e * HF * DM;
    (void)wp;
    float acc[4][4];
    #pragma unroll
    for (int i = 0; i < 4; i++)
        #pragma unroll
        for (int j = 0; j < 4; j++) acc[i][j] = 0.f;
    for (int kk = 0; kk < HF; kk += 16) {
        float4 a4 = *(const float4*)(ap + kk);
        As[lk4 + 0][lrow] = a4.x; As[lk4 + 1][lrow] = a4.y;
        As[lk4 + 2][lrow] = a4.z; As[lk4 + 3][lrow] = a4.w;
        // load B: 16 k-rows x 64 d-cols; w2t row (kk + krow) has d contiguous
        {
            int krow = tid >> 4;        // 0..15
            int dcol = (tid & 15) << 2; // 0,4,...,60
            float4 b4 = *(const float4*)(wbase + (size_t)(kk + krow) * DM + d0 + dcol);
            Bs[krow][dcol + 0] = b4.x; Bs[krow][dcol + 1] = b4.y;
            Bs[krow][dcol + 2] = b4.z; Bs[krow][dcol + 3] = b4.w;
        }
        __syncthreads();
        #pragma unroll
        for (int k = 0; k < 16; k++) {
            float a[4], b[4];
            #pragma unroll
            for (int i = 0; i < 4; i++) a[i] = As[k][ty * 4 + i];
            #pragma unroll
            for (int j = 0; j < 4; j++) b[j] = Bs[k][tx * 4 + j];
            #pragma unroll
            for (int i = 0; i < 4; i++)
                #pragma unroll
                for (int j = 0; j < 4; j++) acc[i][j] += a[i] * b[j];
        }
        __syncthreads();
    }
    #pragma unroll
    for (int i = 0; i < 4; i++) {
        int r = ty * 4 + i;
        if (r < rows) {
            int asn = g_idx_list[r0 + r];
            int n = asn >> 1, kslot = asn & 1;
            float kp = g_keep[asn];
            const float* xr = x + (size_t)n * DM + d0;
            float* tr = g_tokens + ((size_t)n * 3 + kslot) * DM + d0;
            #pragma unroll
            for (int j = 0; j < 4; j++) {
                int d = tx * 4 + j;
                tr[d] = kp * (xr[d] + acc[i][j]);
            }
        }
    }
}

// ---------------- generic NT SGEMM: C[m,n] = sum_k A[m,k]*B[n,k] (+bias)(+res)(gelu) ----------------
template<bool GELU>
__global__ void gemm_nt(const float* __restrict__ A, const float* __restrict__ B,
                        const float* __restrict__ bias, const float* __restrict__ res,
                        float* __restrict__ C, int M, int Nn, int Kk) {
    __shared__ float As[16][64];
    __shared__ float Bs[16][64];
    int tid = threadIdx.x;
    size_t m0 = (size_t)blockIdx.x * 64, n0 = (size_t)blockIdx.y * 64;
    int lrow = tid >> 2, lk4 = (tid & 3) << 2;
    int tx = tid & 15, ty = tid >> 4;
    float acc[4][4];
    #pragma unroll
    for (int i = 0; i < 4; i++)
        #pragma unroll
        for (int j = 0; j < 4; j++) acc[i][j] = 0.f;
    const float* Ap = A + (m0 + lrow) * Kk + lk4;
    const float* Bp = B + (n0 + lrow) * Kk + lk4;
    for (int kk = 0; kk < Kk; kk += 16) {
        float4 a4 = *(const float4*)(Ap + kk);
        float4 b4 = *(const float4*)(Bp + kk);
        As[lk4 + 0][lrow] = a4.x; As[lk4 + 1][lrow] = a4.y;
        As[lk4 + 2][lrow] = a4.z; As[lk4 + 3][lrow] = a4.w;
        Bs[lk4 + 0][lrow] = b4.x; Bs[lk4 + 1][lrow] = b4.y;
        Bs[lk4 + 2][lrow] = b4.z; Bs[lk4 + 3][lrow] = b4.w;
        __syncthreads();
        #pragma unroll
        for (int k = 0; k < 16; k++) {
            float a[4], b[4];
            #pragma unroll
            for (int i = 0; i < 4; i++) a[i] = As[k][ty * 4 + i];
            #pragma unroll
            for (int j = 0; j < 4; j++) b[j] = Bs[k][tx * 4 + j];
            #pragma unroll
            for (int i = 0; i < 4; i++)
                #pragma unroll
                for (int j = 0; j < 4; j++) acc[i][j] += a[i] * b[j];
        }
        __syncthreads();
    }
    #pragma unroll
    for (int i = 0; i < 4; i++) {
        size_t m = m0 + ty * 4 + i;
        #pragma unroll
        for (int j = 0; j < 4; j++) {
            size_t n = n0 + tx * 4 + j;
            float v = acc[i][j];
            if (bias) v += bias[n];
            if (res) v += res[m * Nn + n];
            if (GELU) v = 0.5f * v * (1.f + erff(v * 0.70710678118654752f));
            C[m * Nn + n] = v;
        }
    }
}

// ---------------- tiny 3-token attention (warp per head) ----------------
__global__ void attn_kernel() {
    int n = blockIdx.x;
    int h = threadIdx.x >> 5, lane = threadIdx.x & 31;
    const float* base = g_qkv + (size_t)n * 3 * QKVW;
    float q[3][6], k[3][6], v[3][6];
    #pragma unroll
    for (int li = 0; li < 3; li++) {
        const float* bp = base + (size_t)li * QKVW + h * 192 + lane * 6;
        #pragma unroll
        for (int dd = 0; dd < 6; dd++) {
            q[li][dd] = bp[dd];
            k[li][dd] = bp[dd + DM];
            v[li][dd] = bp[dd + 2 * DM];
        }
    }
    const float scale = 0.07216878364870322f;
    float b0 = (g_keep[2 * n]     > 0.5f) ? 0.f : -1e9f;
    float b1 = (g_keep[2 * n + 1] > 0.5f) ? 0.f : -1e9f;
    float s[3][3];
    #pragma unroll
    for (int qi = 0; qi < 3; qi++) {
        #pragma unroll
        for (int kj = 0; kj < 3; kj++) {
            float t = 0.f;
            #pragma unroll
            for (int dd = 0; dd < 6; dd++) t += q[qi][dd] * k[kj][dd];
            #pragma unroll
            for (int o = 16; o; o >>= 1) t += __shfl_xor_sync(0xffffffffu, t, o);
            s[qi][kj] = t * scale;
        }
        s[qi][0] += b0;
        s[qi][1] += b1;
    }
    #pragma unroll
    for (int qi = 0; qi < 3; qi++) {
        float m = fmaxf(s[qi][0], fmaxf(s[qi][1], s[qi][2]));
        float e0 = expf(s[qi][0] - m), e1 = expf(s[qi][1] - m), e2 = expf(s[qi][2] - m);
        float inv = 1.f / (e0 + e1 + e2);
        float a0 = e0 * inv, a1 = e1 * inv, a2 = e2 * inv;
        float* op = g_attn + (size_t)(n * 3 + qi) * DM + h * 192 + lane * 6;
        #pragma unroll
        for (int dd = 0; dd < 6; dd++)
            op[dd] = a0 * v[0][dd] + a1 * v[1][dd] + a2 * v[2][dd];
    }
}

// ---------------- dual RMSNorm: tokens = rms(tokens,w1); u = rms(tokens,w2) ----------------
__global__ void rms_dual_kernel(const float* __restrict__ w1, const float* __restrict__ w2) {
    __shared__ float sh[8];
    __shared__ float sscale;
    int m = blockIdx.x, tid = threadIdx.x;
    float* row = g_tokens + (size_t)m * DM;
    float v0 = row[tid], v1 = row[tid + 256], v2 = row[tid + 512];
    float ss = v0 * v0 + v1 * v1 + v2 * v2;
    #pragma unroll
    for (int o = 16; o; o >>= 1) ss += __shfl_xor_sync(0xffffffffu, ss, o);
    if ((tid & 31) == 0) sh[tid >> 5] = ss;
    __syncthreads();
    if (tid == 0) {
        float t = 0.f;
        #pragma unroll
        for (int i = 0; i < 8; i++) t += sh[i];
        sscale = rsqrtf(t * (1.f / DM) + 1e-6f);
    }
    __syncthreads();
    float s1 = sscale;
    float t0 = v0 * s1 * w1[tid];
    float t1 = v1 * s1 * w1[tid + 256];
    float t2 = v2 * s1 * w1[tid + 512];
    row[tid] = t0; row[tid + 256] = t1; row[tid + 512] = t2;
    float ss2 = t0 * t0 + t1 * t1 + t2 * t2;
    #pragma unroll
    for (int o = 16; o; o >>= 1) ss2 += __shfl_xor_sync(0xffffffffu, ss2, o);
    __syncthreads();
    if ((tid & 31) == 0) sh[tid >> 5] = ss2;
    __syncthreads();
    if (tid == 0) {
        float t = 0.f;
        #pragma unroll
        for (int i = 0; i < 8; i++) t += sh[i];
        sscale = rsqrtf(t * (1.f / DM) + 1e-6f);
    }
    __syncthreads();
    float s2 = sscale;
    float* ur = g_u + (size_t)m * DM;
    ur[tid]       = t0 * s2 * w2[tid];
    ur[tid + 256] = t1 * s2 * w2[tid + 256];
    ur[tid + 512] = t2 * s2 * w2[tid + 512];
}

// ---------------- fuse prep: fm = g*med + (1-g)*(w0*e0 + w1*e1) ----------------
__global__ void fuse_prep_kernel(const float* __restrict__ fgw, const float* __restrict__ fgb) {
    __shared__ float sh[8];
    __shared__ float par[3];
    int n = blockIdx.x, tid = threadIdx.x;
    const float* med = g_tokens + ((size_t)n * 3 + 2) * DM;
    float s = med[tid] * fgw[tid] + med[tid + 256] * fgw[tid + 256] + med[tid + 512] * fgw[tid + 512];
    #pragma unroll
    for (int o = 16; o; o >>= 1) s += __shfl_xor_sync(0xffffffffu, s, o);
    if ((tid & 31) == 0) sh[tid >> 5] = s;
    __syncthreads();
    if (tid == 0) {
        float t = 0.f;
        #pragma unroll
        for (int i = 0; i < 8; i++) t += sh[i];
        float g = 1.f / (1.f + expf(-(t + fgb[0])));
        float tp0 = g_tpk[2 * n] * g_keep[2 * n];
        float tp1 = g_tpk[2 * n + 1] * g_keep[2 * n + 1];
        float den = tp0 + tp1;
        par[0] = g;
        par[1] = den > 0.f ? tp0 / den : 0.f;
        par[2] = den > 0.f ? tp1 / den : 0.f;
    }
    __syncthreads();
    float g = par[0], w0 = par[1], w1 = par[2];
    const float* e0 = g_tokens + ((size_t)n * 3 + 0) * DM;
    const float* e1 = g_tokens + ((size_t)n * 3 + 1) * DM;
    float* fm = g_fm + (size_t)n * DM;
    #pragma unroll
    for (int c = 0; c < 3; c++) {
        int d = tid + c * 256;
        fm[d] = g * med[d] + (1.f - g) * (w0 * e0[d] + w1 * e1[d]);
    }
}

__global__ void aux_kernel(float* __restrict__ out) {
    if (threadIdx.x != 0 || blockIdx.x != 0) return;
    float bal = 0.f;
    for (int e = 0; e < NE; e++)
        bal += (g_router_sum[e] / (float)NTOK) * (g_assign_sum[e] / (float)NTOK);
    bal *= (float)NE;
    float aux = 0.01f * bal + 0.001f * (g_z2 / (float)NTOK)
              + 0.001f * (1.f - (float)g_keepcnt / (float)NKA);
    out[(size_t)NTOK * DM] = aux;
}

// ---------------- launch ----------------
extern "C" void kernel_launch(void* const* d_in, const int* in_sizes, int n_in,
                              void* d_out, int out_size) {
    const float* x          = (const float*)d_in[0];
    const float* gate_w     = (const float*)d_in[1];
    const float* w13        = (const float*)d_in[2];
    const float* w2         = (const float*)d_in[3];
    const float* in_proj_w  = (const float*)d_in[4];
    const float* in_proj_b  = (const float*)d_in[5];
    const float* out_w      = (const float*)d_in[6];
    const float* out_b      = (const float*)d_in[7];
    const float* norm1_w    = (const float*)d_in[8];
    const float* norm2_w    = (const float*)d_in[9];
    const float* ffn_w1     = (const float*)d_in[10];
    const float* ffn_w2     = (const float*)d_in[11];
    const float* mediator   = (const float*)d_in[12];
    const float* fuse_gate_w= (const float*)d_in[13];
    const float* fuse_gate_b= (const float*)d_in[14];
    const float* o_proj_w   = (const float*)d_in[15];
    float* out = (float*)d_out;

    float *p_tokens, *p_qkv, *p_attn, *p_u, *p_h, *p_fm;
    cudaGetSymbolAddress((void**)&p_tokens, g_tokens);
    cudaGetSymbolAddress((void**)&p_qkv, g_qkv);
    cudaGetSymbolAddress((void**)&p_attn, g_attn);
    cudaGetSymbolAddress((void**)&p_u, g_u);
    cudaGetSymbolAddress((void**)&p_h, g_hbuf);
    cudaGetSymbolAddress((void**)&p_fm, g_fm);

    zero_accum_kernel<<<1, 32>>>();
    w2t_kernel<<<4096, 256>>>(w2);
    med_init_kernel<<<2048, 256>>>(mediator);
    gate_kernel<<<NTOK, 256>>>(x, gate_w, out);
    build_tiles_kernel<<<1, 1>>>();
    scatter_kernel<<<NKA / 256, 256>>>();
    keep_kernel<<<NKA / 256, 256>>>();
    expertA_kernel<<<dim3(264, HF / 64), 256>>>(x, w13);
    expertB_kernel<<<dim3(264, DM / 64), 256>>>(x);

    for (int step = 0; step < 2; step++) {
        gemm_nt<false><<<dim3(MROW / 64, QKVW / 64), 256>>>(
            p_tokens, in_proj_w, in_proj_b, nullptr, p_qkv, MROW, QKVW, DM);
        attn_kernel<<<NTOK, 128>>>();
        gemm_nt<false><<<dim3(MROW / 64, DM / 64), 256>>>(
            p_attn, out_w, out_b, p_tokens, p_tokens, MROW, DM, DM);
        rms_dual_kernel<<<MROW, 256>>>(norm1_w, norm2_w);
        gemm_nt<true><<<dim3(MROW / 64, DM / 64), 256>>>(
            p_u, ffn_w1, nullptr, nullptr, p_h, MROW, DM, DM);
        gemm_nt<false><<<dim3(MROW / 64, DM / 64), 256>>>(
            p_h, ffn_w2, nullptr, p_tokens, p_tokens, MROW, DM, DM);
    }

    fuse_prep_kernel<<<NTOK, 256>>>(fuse_gate_w, fuse_gate_b);
    gemm_nt<false><<<dim3(NTOK / 64, DM / 64), 256>>>(
        p_fm, o_proj_w, nullptr, nullptr, out, NTOK, DM, DM);
    aux_kernel<<<1, 1>>>(out);
}

// round 2
// speedup vs baseline: 3.4763x; 3.4763x over previous
#include <cuda_runtime.h>
#include <math.h>

#define NTOK 8192
#define DM   768
#define NE   8
#define NKA  16384
#define HF   2048
#define CAPC 4096
#define MROW 24576
#define QKVW 2304
#define MAXT 144

// ---------------- scratch ----------------
__device__ float g_router_sum[NE];
__device__ float g_assign_sum[NE];
__device__ float g_z2;
__device__ int   g_counts[NE];
__device__ int   g_fill[NE];
__device__ int   g_offsets[NE];
__device__ int   g_keepcnt;
__device__ int   g_te[NKA];
__device__ float g_prio[NKA];
__device__ float g_tpk[NKA];
__device__ float g_keep[NKA];
__device__ int   g_idx_list[NKA];
__device__ int   g_tile_e[MAXT];
__device__ int   g_tile_r0[MAXT];
__device__ int   g_tile_rows[MAXT];
__device__ int   g_ntiles;

__device__ float g_gu[(size_t)NKA * 2 * HF];
__device__ float g_act[(size_t)(NKA + 128) * HF];
__device__ float g_tokens[(size_t)MROW * DM];
__device__ float g_qkv[(size_t)MROW * QKVW];
__device__ float g_attn[(size_t)MROW * DM];
__device__ float g_u[(size_t)MROW * DM];
__device__ float g_hbuf[(size_t)MROW * DM];
__device__ float g_fm[(size_t)NTOK * DM];

// ---------------- tf32 helpers ----------------
__device__ __forceinline__ unsigned tf32cvt(float f) {
    unsigned u;
    asm("cvt.rna.tf32.f32 %0, %1;" : "=r"(u) : "f"(f));
    return u;
}
__device__ __forceinline__ void st_tf32(unsigned* S, int idx, float4 v, float alpha) {
    uint4 u;
    u.x = tf32cvt(alpha * v.x); u.y = tf32cvt(alpha * v.y);
    u.z = tf32cvt(alpha * v.z); u.w = tf32cvt(alpha * v.w);
    *(uint4*)(S + idx) = u;
}
__device__ __forceinline__ void mma8(float* c, const unsigned* a, const unsigned* b) {
    asm volatile(
        "mma.sync.aligned.m16n8k8.row.col.f32.tf32.tf32.f32 "
        "{%0,%1,%2,%3},{%4,%5,%6,%7},{%8,%9},{%0,%1,%2,%3};"
        : "+f"(c[0]), "+f"(c[1]), "+f"(c[2]), "+f"(c[3])
        : "r"(a[0]), "r"(a[1]), "r"(a[2]), "r"(a[3]), "r"(b[0]), "r"(b[1]));
}

// mma over one 128x128x32 smem tile (8 warps, warp tile 64x32)
__device__ __forceinline__ void mma_tile(const unsigned* As, const unsigned* Bs,
                                         float acc[4][4][4], int lane, int warpM, int warpN) {
    int lr = lane >> 2, lk = lane & 3;
    #pragma unroll
    for (int ks = 0; ks < 4; ks++) {
        int k = ks * 8 + lk;
        unsigned a[4][4], b[4][2];
        #pragma unroll
        for (int mf = 0; mf < 4; mf++) {
            int rb = warpM * 64 + mf * 16 + lr;
            a[mf][0] = As[rb * 36 + k];
            a[mf][1] = As[(rb + 8) * 36 + k];
            a[mf][2] = As[rb * 36 + k + 4];
            a[mf][3] = As[(rb + 8) * 36 + k + 4];
        }
        #pragma unroll
        for (int nf = 0; nf < 4; nf++) {
            int cb = warpN * 32 + nf * 8 + lr;
            b[nf][0] = Bs[cb * 36 + k];
            b[nf][1] = Bs[cb * 36 + k + 4];
        }
        #pragma unroll
        for (int mf = 0; mf < 4; mf++)
            #pragma unroll
            for (int nf = 0; nf < 4; nf++)
                mma8(acc[mf][nf], a[mf], b[nf]);
    }
}

// ---------------- generic NT GEMM (tensor core) ----------------
template<bool GELU>
__global__ void __launch_bounds__(256) gemm_tc(
    const float* __restrict__ A, const float* __restrict__ B,
    const float* __restrict__ bias, const float* __restrict__ res,
    float* __restrict__ C, int N, int K)
{
    __shared__ unsigned As[128 * 36];
    __shared__ unsigned Bs[128 * 36];
    int tid = threadIdx.x, lane = tid & 31, warp = tid >> 5;
    int warpM = warp >> 2, warpN = warp & 3;
    size_t m0 = (size_t)blockIdx.x * 128;
    int n0 = blockIdx.y * 128;
    float acc[4][4][4] = {};
    const float* Ab = A + m0 * K;
    const float* Bb = B + (size_t)n0 * K;
    int r = tid >> 3, c4 = (tid & 7) * 4;
    float4 ar[4], br[4];
    #pragma unroll
    for (int i = 0; i < 4; i++) {
        ar[i] = *(const float4*)(Ab + (size_t)(r + i * 32) * K + c4);
        br[i] = *(const float4*)(Bb + (size_t)(r + i * 32) * K + c4);
    }
    for (int kk = 0; kk < K; kk += 32) {
        #pragma unroll
        for (int i = 0; i < 4; i++) {
            st_tf32(As, (r + i * 32) * 36 + c4, ar[i], 1.f);
            st_tf32(Bs, (r + i * 32) * 36 + c4, br[i], 1.f);
        }
        __syncthreads();
        if (kk + 32 < K) {
            #pragma unroll
            for (int i = 0; i < 4; i++) {
                ar[i] = *(const float4*)(Ab + (size_t)(r + i * 32) * K + kk + 32 + c4);
                br[i] = *(const float4*)(Bb + (size_t)(r + i * 32) * K + kk + 32 + c4);
            }
        }
        mma_tile(As, Bs, acc, lane, warpM, warpN);
        __syncthreads();
    }
    int lr = lane >> 2, lc = (lane & 3) * 2;
    #pragma unroll
    for (int mf = 0; mf < 4; mf++)
        #pragma unroll
        for (int h = 0; h < 2; h++) {
            size_t m = m0 + warpM * 64 + mf * 16 + lr + h * 8;
            #pragma unroll
            for (int nf = 0; nf < 4; nf++) {
                int col = n0 + warpN * 32 + nf * 8 + lc;
                float v0 = acc[mf][nf][h * 2], v1 = acc[mf][nf][h * 2 + 1];
                if (bias) { v0 += bias[col]; v1 += bias[col + 1]; }
                if (res)  { v0 += res[m * N + col]; v1 += res[m * N + col + 1]; }
                if (GELU) {
                    v0 = 0.5f * v0 * (1.f + erff(v0 * 0.70710678118654752f));
                    v1 = 0.5f * v1 * (1.f + erff(v1 * 0.70710678118654752f));
                }
                *(float2*)(C + m * N + col) = make_float2(v0, v1);
            }
        }
}

// ---------------- expert pass A: gu = 2x @ w13^T (gathered rows) ----------------
__global__ void __launch_bounds__(256) expA_tc(const float* __restrict__ x,
                                               const float* __restrict__ w13)
{
    int t = blockIdx.x;
    if (t >= g_ntiles) return;
    int e = g_tile_e[t], r0 = g_tile_r0[t], rows = g_tile_rows[t];
    int n0 = blockIdx.y * 128;
    __shared__ unsigned As[128 * 36];
    __shared__ unsigned Bs[128 * 36];
    __shared__ int tok[128];
    int tid = threadIdx.x, lane = tid & 31, warp = tid >> 5;
    int warpM = warp >> 2, warpN = warp & 3;
    if (tid < 128) tok[tid] = (tid < rows) ? (g_idx_list[r0 + tid] >> 1) : 0;
    __syncthreads();
    float acc[4][4][4] = {};
    const float* Bb = w13 + (size_t)e * 2 * HF * DM + (size_t)n0 * DM;
    int r = tid >> 3, c4 = (tid & 7) * 4;
    int t0 = tok[r], t1 = tok[r + 32], t2 = tok[r + 64], t3 = tok[r + 96];
    float4 ar[4], br[4];
    ar[0] = *(const float4*)(x + (size_t)t0 * DM + c4);
    ar[1] = *(const float4*)(x + (size_t)t1 * DM + c4);
    ar[2] = *(const float4*)(x + (size_t)t2 * DM + c4);
    ar[3] = *(const float4*)(x + (size_t)t3 * DM + c4);
    #pragma unroll
    for (int i = 0; i < 4; i++)
        br[i] = *(const float4*)(Bb + (size_t)(r + i * 32) * DM + c4);
    for (int kk = 0; kk < DM; kk += 32) {
        #pragma unroll
        for (int i = 0; i < 4; i++) {
            st_tf32(As, (r + i * 32) * 36 + c4, ar[i], 2.f);
            st_tf32(Bs, (r + i * 32) * 36 + c4, br[i], 1.f);
        }
        __syncthreads();
        if (kk + 32 < DM) {
            ar[0] = *(const float4*)(x + (size_t)t0 * DM + kk + 32 + c4);
            ar[1] = *(const float4*)(x + (size_t)t1 * DM + kk + 32 + c4);
            ar[2] = *(const float4*)(x + (size_t)t2 * DM + kk + 32 + c4);
            ar[3] = *(const float4*)(x + (size_t)t3 * DM + kk + 32 + c4);
            #pragma unroll
            for (int i = 0; i < 4; i++)
                br[i] = *(const float4*)(Bb + (size_t)(r + i * 32) * DM + kk + 32 + c4);
        }
        mma_tile(As, Bs, acc, lane, warpM, warpN);
        __syncthreads();
    }
    int lr = lane >> 2, lc = (lane & 3) * 2;
    #pragma unroll
    for (int mf = 0; mf < 4; mf++)
        #pragma unroll
        for (int h = 0; h < 2; h++) {
            int rl = warpM * 64 + mf * 16 + lr + h * 8;
            if (rl < rows) {
                float* cp = g_gu + (size_t)(r0 + rl) * (2 * HF) + n0;
                #pragma unroll
                for (int nf = 0; nf < 4; nf++) {
                    int col = warpN * 32 + nf * 8 + lc;
                    *(float2*)(cp + col) =
                        make_float2(acc[mf][nf][h * 2], acc[mf][nf][h * 2 + 1]);
                }
            }
        }
}

// ---------------- silu: act = silu(gate)*up ----------------
__global__ void silu_kernel() {
    size_t i = (size_t)blockIdx.x * blockDim.x + threadIdx.x;  // over NKA*HF/4
    size_t rr = i >> 9;            // HF/4 = 512
    size_t h4 = i & 511;
    const float4* gu4 = (const float4*)g_gu;
    float4 gv = gu4[rr * 1024 + h4];
    float4 uv = gu4[rr * 1024 + 512 + h4];
    float4 o;
    o.x = gv.x / (1.f + expf(-gv.x)) * uv.x;
    o.y = gv.y / (1.f + expf(-gv.y)) * uv.y;
    o.z = gv.z / (1.f + expf(-gv.z)) * uv.z;
    o.w = gv.w / (1.f + expf(-gv.w)) * uv.w;
    ((float4*)g_act)[rr * 512 + h4] = o;
}

// ---------------- expert pass B: tokens[slot] = keep*(x + act @ w2^T) ----------------
__global__ void __launch_bounds__(256) expB_tc(const float* __restrict__ x,
                                               const float* __restrict__ w2)
{
    int t = blockIdx.x;
    if (t >= g_ntiles) return;
    int e = g_tile_e[t], r0 = g_tile_r0[t], rows = g_tile_rows[t];
    int n0 = blockIdx.y * 128;
    __shared__ unsigned As[128 * 36];
    __shared__ unsigned Bs[128 * 36];
    __shared__ int s_asn[128];
    int tid = threadIdx.x, lane = tid & 31, warp = tid >> 5;
    int warpM = warp >> 2, warpN = warp & 3;
    if (tid < 128) s_asn[tid] = (tid < rows) ? g_idx_list[r0 + tid] : 0;
    float acc[4][4][4] = {};
    const float* Ab = g_act + (size_t)r0 * HF;
    const float* Bb = w2 + (size_t)e * DM * HF + (size_t)n0 * HF;
    int r = tid >> 3, c4 = (tid & 7) * 4;
    float4 ar[4], br[4];
    #pragma unroll
    for (int i = 0; i < 4; i++) {
        ar[i] = *(const float4*)(Ab + (size_t)(r + i * 32) * HF + c4);
        br[i] = *(const float4*)(Bb + (size_t)(r + i * 32) * HF + c4);
    }
    for (int kk = 0; kk < HF; kk += 32) {
        #pragma unroll
        for (int i = 0; i < 4; i++) {
            st_tf32(As, (r + i * 32) * 36 + c4, ar[i], 1.f);
            st_tf32(Bs, (r + i * 32) * 36 + c4, br[i], 1.f);
        }
        __syncthreads();
        if (kk + 32 < HF) {
            #pragma unroll
            for (int i = 0; i < 4; i++) {
                ar[i] = *(const float4*)(Ab + (size_t)(r + i * 32) * HF + kk + 32 + c4);
                br[i] = *(const float4*)(Bb + (size_t)(r + i * 32) * HF + kk + 32 + c4);
            }
        }
        mma_tile(As, Bs, acc, lane, warpM, warpN);
        __syncthreads();
    }
    int lr = lane >> 2, lc = (lane & 3) * 2;
    #pragma unroll
    for (int mf = 0; mf < 4; mf++)
        #pragma unroll
        for (int h = 0; h < 2; h++) {
            int rl = warpM * 64 + mf * 16 + lr + h * 8;
            if (rl < rows) {
                int asn = s_asn[rl];
                int n = asn >> 1, slot = asn & 1;
                float kp = g_keep[asn];
                const float* xr = x + (size_t)n * DM + n0;
                float* tr = g_tokens + ((size_t)n * 3 + slot) * DM + n0;
                #pragma unroll
                for (int nf = 0; nf < 4; nf++) {
                    int col = warpN * 32 + nf * 8 + lc;
                    tr[col]     = kp * (xr[col]     + acc[mf][nf][h * 2]);
                    tr[col + 1] = kp * (xr[col + 1] + acc[mf][nf][h * 2 + 1]);
                }
            }
        }
}

// ---------------- small kernels ----------------
__global__ void zero_accum_kernel() {
    int t = threadIdx.x;
    if (t < NE) { g_router_sum[t] = 0.f; g_assign_sum[t] = 0.f; g_counts[t] = 0; g_fill[t] = 0; }
    if (t == 0) { g_z2 = 0.f; g_keepcnt = 0; }
}

__global__ void med_init_kernel(const float* __restrict__ mediator) {
    size_t total = (size_t)NTOK * DM;
    for (size_t i = blockIdx.x * blockDim.x + threadIdx.x; i < total; i += (size_t)gridDim.x * blockDim.x) {
        size_t n = i / DM;
        size_t d = i - n * DM;
        g_tokens[(n * 3 + 2) * DM + d] = mediator[d];
    }
}

__global__ void gate_kernel(const float* __restrict__ x, const float* __restrict__ gw,
                            float* __restrict__ out) {
    __shared__ float xs[DM];
    __shared__ float lg[NE];
    int n = blockIdx.x, tid = threadIdx.x;
    for (int i = tid; i < DM; i += 256) xs[i] = x[(size_t)n * DM + i];
    __syncthreads();
    int w = tid >> 5, lane = tid & 31;
    const float* g = gw + (size_t)w * DM;
    float s = 0.f;
    for (int i = lane; i < DM; i += 32) s += xs[i] * g[i];
    #pragma unroll
    for (int o = 16; o; o >>= 1) s += __shfl_xor_sync(0xffffffffu, s, o);
    if (lane == 0) lg[w] = s;
    __syncthreads();
    if (tid == 0) {
        float l[NE];
        #pragma unroll
        for (int e = 0; e < NE; e++) l[e] = lg[e];
        int i1 = 0; float v1 = l[0];
        for (int e = 1; e < NE; e++) if (l[e] > v1) { v1 = l[e]; i1 = e; }
        int i2 = -1; float v2 = -3.4e38f;
        for (int e = 0; e < NE; e++) if (e != i1 && l[e] > v2) { v2 = l[e]; i2 = e; }
        float e2 = expf(v2 - v1);
        float inv = 1.f / (1.f + e2);
        float p1 = inv, p2 = e2 * inv;
        float se = 0.f;
        for (int e = 0; e < NE; e++) se += expf(l[e] - v1);
        float z = v1 + logf(se);
        for (int e = 0; e < NE; e++) atomicAdd(&g_router_sum[e], expf(l[e] - v1) / se);
        atomicAdd(&g_assign_sum[i1], p1);
        atomicAdd(&g_assign_sum[i2], p2);
        atomicAdd(&g_z2, z * z);
        atomicAdd(&g_counts[i1], 1);
        atomicAdd(&g_counts[i2], 1);
        g_te[2 * n] = i1; g_te[2 * n + 1] = i2;
        g_prio[2 * n] = v1; g_prio[2 * n + 1] = v2;
        g_tpk[2 * n] = p1; g_tpk[2 * n + 1] = p2;
        out[(size_t)NTOK * DM + 1 + 2 * n]     = (float)i1;
        out[(size_t)NTOK * DM + 1 + 2 * n + 1] = (float)i2;
    }
}

__global__ void build_tiles_kernel() {
    if (threadIdx.x != 0 || blockIdx.x != 0) return;
    int off = 0, nt = 0;
    for (int e = 0; e < NE; e++) {
        g_offsets[e] = off;
        int c = g_counts[e];
        int ntile = (c + 127) >> 7;
        for (int t = 0; t < ntile; t++) {
            g_tile_e[nt] = e;
            g_tile_r0[nt] = off + t * 128;
            int r = c - t * 128;
            g_tile_rows[nt] = r < 128 ? r : 128;
            nt++;
        }
        off += c;
    }
    g_ntiles = nt;
}

__global__ void scatter_kernel() {
    int i = blockIdx.x * 256 + threadIdx.x;
    if (i >= NKA) return;
    int e = g_te[i];
    int p = atomicAdd(&g_fill[e], 1);
    g_idx_list[g_offsets[e] + p] = i;
}

__global__ void keep_kernel() {
    int i = blockIdx.x * 256 + threadIdx.x;
    if (i >= NKA) return;
    int e = g_te[i];
    int kp;
    if (g_counts[e] <= CAPC) {
        kp = 1;
    } else {
        float pi = g_prio[i];
        int rank = 0;
        for (int j = 0; j < NKA; j++) {
            if (g_te[j] == e) {
                float pj = g_prio[j];
                if (pj > pi || (pj == pi && j < i)) rank++;
            }
        }
        kp = (rank < CAPC) ? 1 : 0;
    }
    g_keep[i] = (float)kp;
    atomicAdd(&g_keepcnt, kp);
}

__global__ void attn_kernel() {
    int n = blockIdx.x;
    int h = threadIdx.x >> 5, lane = threadIdx.x & 31;
    const float* base = g_qkv + (size_t)n * 3 * QKVW;
    float q[3][6], k[3][6], v[3][6];
    #pragma unroll
    for (int li = 0; li < 3; li++) {
        const float* bp = base + (size_t)li * QKVW + h * 192 + lane * 6;
        #pragma unroll
        for (int dd = 0; dd < 6; dd++) {
            q[li][dd] = bp[dd];
            k[li][dd] = bp[dd + DM];
            v[li][dd] = bp[dd + 2 * DM];
        }
    }
    const float scale = 0.07216878364870322f;
    float b0 = (g_keep[2 * n]     > 0.5f) ? 0.f : -1e9f;
    float b1 = (g_keep[2 * n + 1] > 0.5f) ? 0.f : -1e9f;
    float s[3][3];
    #pragma unroll
    for (int qi = 0; qi < 3; qi++) {
        #pragma unroll
        for (int kj = 0; kj < 3; kj++) {
            float t = 0.f;
            #pragma unroll
            for (int dd = 0; dd < 6; dd++) t += q[qi][dd] * k[kj][dd];
            #pragma unroll
            for (int o = 16; o; o >>= 1) t += __shfl_xor_sync(0xffffffffu, t, o);
            s[qi][kj] = t * scale;
        }
        s[qi][0] += b0;
        s[qi][1] += b1;
    }
    #pragma unroll
    for (int qi = 0; qi < 3; qi++) {
        float m = fmaxf(s[qi][0], fmaxf(s[qi][1], s[qi][2]));
        float e0 = expf(s[qi][0] - m), e1 = expf(s[qi][1] - m), e2 = expf(s[qi][2] - m);
        float inv = 1.f / (e0 + e1 + e2);
        float a0 = e0 * inv, a1 = e1 * inv, a2 = e2 * inv;
        float* op = g_attn + (size_t)(n * 3 + qi) * DM + h * 192 + lane * 6;
        #pragma unroll
        for (int dd = 0; dd < 6; dd++)
            op[dd] = a0 * v[0][dd] + a1 * v[1][dd] + a2 * v[2][dd];
    }
}

__global__ void rms_dual_kernel(const float* __restrict__ w1, const float* __restrict__ w2) {
    __shared__ float sh[8];
    __shared__ float sscale;
    int m = blockIdx.x, tid = threadIdx.x;
    float* row = g_tokens + (size_t)m * DM;
    float v0 = row[tid], v1 = row[tid + 256], v2 = row[tid + 512];
    float ss = v0 * v0 + v1 * v1 + v2 * v2;
    #pragma unroll
    for (int o = 16; o; o >>= 1) ss += __shfl_xor_sync(0xffffffffu, ss, o);
    if ((tid & 31) == 0) sh[tid >> 5] = ss;
    __syncthreads();
    if (tid == 0) {
        float t = 0.f;
        #pragma unroll
        for (int i = 0; i < 8; i++) t += sh[i];
        sscale = rsqrtf(t * (1.f / DM) + 1e-6f);
    }
    __syncthreads();
    float s1 = sscale;
    float t0 = v0 * s1 * w1[tid];
    float t1 = v1 * s1 * w1[tid + 256];
    float t2 = v2 * s1 * w1[tid + 512];
    row[tid] = t0; row[tid + 256] = t1; row[tid + 512] = t2;
    float ss2 = t0 * t0 + t1 * t1 + t2 * t2;
    #pragma unroll
    for (int o = 16; o; o >>= 1) ss2 += __shfl_xor_sync(0xffffffffu, ss2, o);
    __syncthreads();
    if ((tid & 31) == 0) sh[tid >> 5] = ss2;
    __syncthreads();
    if (tid == 0) {
        float t = 0.f;
        #pragma unroll
        for (int i = 0; i < 8; i++) t += sh[i];
        sscale = rsqrtf(t * (1.f / DM) + 1e-6f);
    }
    __syncthreads();
    float s2 = sscale;
    float* ur = g_u + (size_t)m * DM;
    ur[tid]       = t0 * s2 * w2[tid];
    ur[tid + 256] = t1 * s2 * w2[tid + 256];
    ur[tid + 512] = t2 * s2 * w2[tid + 512];
}

__global__ void fuse_prep_kernel(const float* __restrict__ fgw, const float* __restrict__ fgb) {
    __shared__ float sh[8];
    __shared__ float par[3];
    int n = blockIdx.x, tid = threadIdx.x;
    const float* med = g_tokens + ((size_t)n * 3 + 2) * DM;
    float s = med[tid] * fgw[tid] + med[tid + 256] * fgw[tid + 256] + med[tid + 512] * fgw[tid + 512];
    #pragma unroll
    for (int o = 16; o; o >>= 1) s += __shfl_xor_sync(0xffffffffu, s, o);
    if ((tid & 31) == 0) sh[tid >> 5] = s;
    __syncthreads();
    if (tid == 0) {
        float t = 0.f;
        #pragma unroll
        for (int i = 0; i < 8; i++) t += sh[i];
        float g = 1.f / (1.f + expf(-(t + fgb[0])));
        float tp0 = g_tpk[2 * n] * g_keep[2 * n];
        float tp1 = g_tpk[2 * n + 1] * g_keep[2 * n + 1];
        float den = tp0 + tp1;
        par[0] = g;
        par[1] = den > 0.f ? tp0 / den : 0.f;
        par[2] = den > 0.f ? tp1 / den : 0.f;
    }
    __syncthreads();
    float g = par[0], w0 = par[1], w1 = par[2];
    const float* e0 = g_tokens + ((size_t)n * 3 + 0) * DM;
    const float* e1 = g_tokens + ((size_t)n * 3 + 1) * DM;
    float* fm = g_fm + (size_t)n * DM;
    #pragma unroll
    for (int c = 0; c < 3; c++) {
        int d = tid + c * 256;
        fm[d] = g * med[d] + (1.f - g) * (w0 * e0[d] + w1 * e1[d]);
    }
}

__global__ void aux_kernel(float* __restrict__ out) {
    if (threadIdx.x != 0 || blockIdx.x != 0) return;
    float bal = 0.f;
    for (int e = 0; e < NE; e++)
        bal += (g_router_sum[e] / (float)NTOK) * (g_assign_sum[e] / (float)NTOK);
    bal *= (float)NE;
    float aux = 0.01f * bal + 0.001f * (g_z2 / (float)NTOK)
              + 0.001f * (1.f - (float)g_keepcnt / (float)NKA);
    out[(size_t)NTOK * DM] = aux;
}

// ---------------- launch ----------------
extern "C" void kernel_launch(void* const* d_in, const int* in_sizes, int n_in,
                              void* d_out, int out_size) {
    const float* x          = (const float*)d_in[0];
    const float* gate_w     = (const float*)d_in[1];
    const float* w13        = (const float*)d_in[2];
    const float* w2         = (const float*)d_in[3];
    const float* in_proj_w  = (const float*)d_in[4];
    const float* in_proj_b  = (const float*)d_in[5];
    const float* out_w      = (const float*)d_in[6];
    const float* out_b      = (const float*)d_in[7];
    const float* norm1_w    = (const float*)d_in[8];
    const float* norm2_w    = (const float*)d_in[9];
    const float* ffn_w1     = (const float*)d_in[10];
    const float* ffn_w2     = (const float*)d_in[11];
    const float* mediator   = (const float*)d_in[12];
    const float* fuse_gate_w= (const float*)d_in[13];
    const float* fuse_gate_b= (const float*)d_in[14];
    const float* o_proj_w   = (const float*)d_in[15];
    float* out = (float*)d_out;

    float *p_tokens, *p_qkv, *p_attn, *p_u, *p_h, *p_fm;
    cudaGetSymbolAddress((void**)&p_tokens, g_tokens);
    cudaGetSymbolAddress((void**)&p_qkv, g_qkv);
    cudaGetSymbolAddress((void**)&p_attn, g_attn);
    cudaGetSymbolAddress((void**)&p_u, g_u);
    cudaGetSymbolAddress((void**)&p_h, g_hbuf);
    cudaGetSymbolAddress((void**)&p_fm, g_fm);

    zero_accum_kernel<<<1, 32>>>();
    gate_kernel<<<NTOK, 256>>>(x, gate_w, out);
    build_tiles_kernel<<<1, 1>>>();
    scatter_kernel<<<NKA / 256, 256>>>();
    keep_kernel<<<NKA / 256, 256>>>();
    med_init_kernel<<<2048, 256>>>(mediator);

    expA_tc<<<dim3(136, 2 * HF / 128), 256>>>(x, w13);
    silu_kernel<<<32768, 256>>>();
    expB_tc<<<dim3(136, DM / 128), 256>>>(x, w2);

    for (int step = 0; step < 2; step++) {
        gemm_tc<false><<<dim3(MROW / 128, QKVW / 128), 256>>>(
            p_tokens, in_proj_w, in_proj_b, nullptr, p_qkv, QKVW, DM);
        attn_kernel<<<NTOK, 128>>>();
        gemm_tc<false><<<dim3(MROW / 128, DM / 128), 256>>>(
            p_attn, out_w, out_b, p_tokens, p_tokens, DM, DM);
        rms_dual_kernel<<<MROW, 256>>>(norm1_w, norm2_w);
        gemm_tc<true><<<dim3(MROW / 128, DM / 128), 256>>>(
            p_u, ffn_w1, nullptr, nullptr, p_h, DM, DM);
        gemm_tc<false><<<dim3(MROW / 128, DM / 128), 256>>>(
            p_h, ffn_w2, nullptr, p_tokens, p_tokens, DM, DM);
    }

    fuse_prep_kernel<<<NTOK, 256>>>(fuse_gate_w, fuse_gate_b);
    gemm_tc<false><<<dim3(NTOK / 128, DM / 128), 256>>>(
        p_fm, o_proj_w, nullptr, nullptr, out, DM, DM);
    aux_kernel<<<1, 1>>>(out);
}

// round 3
// speedup vs baseline: 3.6904x; 1.0616x over previous
#include <cuda_runtime.h>
#include <math.h>

#define NTOK 8192
#define DM   768
#define NE   8
#define NKA  16384
#define HF   2048
#define CAPC 4096
#define MROW 24576
#define QKVW 2304
#define MAXT 144
#define STG  4608            // 128*36 unsigned per stage

// ---------------- scratch ----------------
__device__ float g_router_sum[NE];
__device__ float g_assign_sum[NE];
__device__ float g_z2;
__device__ int   g_counts[NE];
__device__ int   g_fill[NE];
__device__ int   g_offsets[NE];
__device__ int   g_keepcnt;
__device__ int   g_te[NKA];
__device__ float g_prio[NKA];
__device__ float g_tpk[NKA];
__device__ float g_keep[NKA];
__device__ int   g_idx_list[NKA];
__device__ int   g_tile_e[MAXT];
__device__ int   g_tile_r0[MAXT];
__device__ int   g_tile_rows[MAXT];
__device__ int   g_ntiles;

__device__ float g_gu[(size_t)NKA * 2 * HF];
__device__ float g_act[(size_t)(NKA + 128) * HF];
__device__ float g_tokens[(size_t)MROW * DM];
__device__ float g_qkv[(size_t)MROW * QKVW];
__device__ float g_attn[(size_t)MROW * DM];
__device__ float g_u[(size_t)MROW * DM];
__device__ float g_hbuf[(size_t)MROW * DM];
__device__ float g_fm[(size_t)NTOK * DM];

// pre-rounded (tf32-valued fp32) copies
__device__ float g_xc[(size_t)NTOK * DM];
__device__ float g_w13c[(size_t)NE * 2 * HF * DM];
__device__ float g_w2c[(size_t)NE * DM * HF];
__device__ float g_ipwc[(size_t)QKVW * DM];
__device__ float g_owc[(size_t)DM * DM];
__device__ float g_f1c[(size_t)DM * DM];
__device__ float g_f2c[(size_t)DM * DM];
__device__ float g_opc[(size_t)DM * DM];

// ---------------- tf32 helpers ----------------
__device__ __forceinline__ unsigned tf32cvt(float f) {
    unsigned u;
    asm("cvt.rna.tf32.f32 %0, %1;" : "=r"(u) : "f"(f));
    return u;
}
__device__ __forceinline__ float tf32r(float f) { return __uint_as_float(tf32cvt(f)); }
__device__ __forceinline__ void st_tf32(unsigned* S, int idx, float4 v) {
    uint4 u;
    u.x = tf32cvt(v.x); u.y = tf32cvt(v.y);
    u.z = tf32cvt(v.z); u.w = tf32cvt(v.w);
    *(uint4*)(S + idx) = u;
}
__device__ __forceinline__ void st_raw(unsigned* S, int idx, float4 v) {
    *(float4*)(S + idx) = v;
}
__device__ __forceinline__ void mma8(float* c, const unsigned* a, const unsigned* b) {
    asm volatile(
        "mma.sync.aligned.m16n8k8.row.col.f32.tf32.tf32.f32 "
        "{%0,%1,%2,%3},{%4,%5,%6,%7},{%8,%9},{%0,%1,%2,%3};"
        : "+f"(c[0]), "+f"(c[1]), "+f"(c[2]), "+f"(c[3])
        : "r"(a[0]), "r"(a[1]), "r"(a[2]), "r"(a[3]), "r"(b[0]), "r"(b[1]));
}

__device__ __forceinline__ void mma_tile(const unsigned* As, const unsigned* Bs,
                                         float acc[4][4][4], int lane, int warpM, int warpN) {
    int lr = lane >> 2, lk = lane & 3;
    #pragma unroll
    for (int ks = 0; ks < 4; ks++) {
        int k = ks * 8 + lk;
        unsigned a[4][4], b[4][2];
        #pragma unroll
        for (int mf = 0; mf < 4; mf++) {
            int rb = warpM * 64 + mf * 16 + lr;
            a[mf][0] = As[rb * 36 + k];
            a[mf][1] = As[(rb + 8) * 36 + k];
            a[mf][2] = As[rb * 36 + k + 4];
            a[mf][3] = As[(rb + 8) * 36 + k + 4];
        }
        #pragma unroll
        for (int nf = 0; nf < 4; nf++) {
            int cb = warpN * 32 + nf * 8 + lr;
            b[nf][0] = Bs[cb * 36 + k];
            b[nf][1] = Bs[cb * 36 + k + 4];
        }
        #pragma unroll
        for (int mf = 0; mf < 4; mf++)
            #pragma unroll
            for (int nf = 0; nf < 4; nf++)
                mma8(acc[mf][nf], a[mf], b[nf]);
    }
}

// ---------------- cvt (pre-round) ----------------
__global__ void cvt_kernel(const float* __restrict__ s, float* __restrict__ d,
                           int n4, float alpha) {
    int i = blockIdx.x * 256 + threadIdx.x;
    if (i >= n4) return;
    float4 v = ((const float4*)s)[i];
    uint4 u;
    u.x = tf32cvt(alpha * v.x); u.y = tf32cvt(alpha * v.y);
    u.z = tf32cvt(alpha * v.z); u.w = tf32cvt(alpha * v.w);
    ((uint4*)d)[i] = u;
}

// ---------------- generic NT GEMM, double-buffered ----------------
template<bool GELU, bool CVTA, bool CVTC>
__global__ void __launch_bounds__(256) gemm_tc(
    const float* __restrict__ A, const float* __restrict__ B,
    const float* __restrict__ bias, const float* __restrict__ res,
    float* __restrict__ C, int N, int K)
{
    extern __shared__ unsigned sm[];
    unsigned* As = sm;
    unsigned* Bs = sm + 2 * STG;
    int tid = threadIdx.x, lane = tid & 31, warp = tid >> 5;
    int warpM = warp >> 2, warpN = warp & 3;
    size_t m0 = (size_t)blockIdx.x * 128;
    int n0 = blockIdx.y * 128;
    const float* Ab = A + m0 * K;
    const float* Bb = B + (size_t)n0 * K;
    int r = tid >> 3, c4 = (tid & 7) * 4;
    float acc[4][4][4] = {};
    float4 ar[4], br[4];
    #pragma unroll
    for (int i = 0; i < 4; i++) {
        ar[i] = *(const float4*)(Ab + (size_t)(r + i * 32) * K + c4);
        br[i] = *(const float4*)(Bb + (size_t)(r + i * 32) * K + c4);
    }
    #pragma unroll
    for (int i = 0; i < 4; i++) {
        if (CVTA) st_tf32(As, (r + i * 32) * 36 + c4, ar[i]);
        else      st_raw (As, (r + i * 32) * 36 + c4, ar[i]);
        st_raw(Bs, (r + i * 32) * 36 + c4, br[i]);
    }
    __syncthreads();
    int stage = 0;
    for (int kk = 0; kk < K; kk += 32) {
        if (kk + 32 < K) {
            #pragma unroll
            for (int i = 0; i < 4; i++) {
                ar[i] = *(const float4*)(Ab + (size_t)(r + i * 32) * K + kk + 32 + c4);
                br[i] = *(const float4*)(Bb + (size_t)(r + i * 32) * K + kk + 32 + c4);
            }
        }
        mma_tile(As + stage * STG, Bs + stage * STG, acc, lane, warpM, warpN);
        if (kk + 32 < K) {
            int ns = stage ^ 1;
            #pragma unroll
            for (int i = 0; i < 4; i++) {
                if (CVTA) st_tf32(As + ns * STG, (r + i * 32) * 36 + c4, ar[i]);
                else      st_raw (As + ns * STG, (r + i * 32) * 36 + c4, ar[i]);
                st_raw(Bs + ns * STG, (r + i * 32) * 36 + c4, br[i]);
            }
        }
        __syncthreads();
        stage ^= 1;
    }
    int lr = lane >> 2, lc = (lane & 3) * 2;
    #pragma unroll
    for (int mf = 0; mf < 4; mf++)
        #pragma unroll
        for (int h = 0; h < 2; h++) {
            size_t m = m0 + warpM * 64 + mf * 16 + lr + h * 8;
            #pragma unroll
            for (int nf = 0; nf < 4; nf++) {
                int col = n0 + warpN * 32 + nf * 8 + lc;
                float v0 = acc[mf][nf][h * 2], v1 = acc[mf][nf][h * 2 + 1];
                if (bias) { v0 += bias[col]; v1 += bias[col + 1]; }
                if (res)  { v0 += res[m * N + col]; v1 += res[m * N + col + 1]; }
                if (GELU) {
                    v0 = 0.5f * v0 * (1.f + erff(v0 * 0.70710678118654752f));
                    v1 = 0.5f * v1 * (1.f + erff(v1 * 0.70710678118654752f));
                }
                if (CVTC) { v0 = tf32r(v0); v1 = tf32r(v1); }
                *(float2*)(C + m * N + col) = make_float2(v0, v1);
            }
        }
}

// ---------------- expert pass A (gathered rows, pre-rounded inputs) ----------------
__global__ void __launch_bounds__(256) expA_tc()
{
    int t = blockIdx.x;
    if (t >= g_ntiles) return;
    int e = g_tile_e[t], r0 = g_tile_r0[t], rows = g_tile_rows[t];
    int n0 = blockIdx.y * 128;
    extern __shared__ unsigned sm[];
    unsigned* As = sm;
    unsigned* Bs = sm + 2 * STG;
    __shared__ int tok[128];
    int tid = threadIdx.x, lane = tid & 31, warp = tid >> 5;
    int warpM = warp >> 2, warpN = warp & 3;
    if (tid < 128) tok[tid] = (tid < rows) ? (g_idx_list[r0 + tid] >> 1) : 0;
    __syncthreads();
    float acc[4][4][4] = {};
    const float* Bb = g_w13c + (size_t)e * 2 * HF * DM + (size_t)n0 * DM;
    int r = tid >> 3, c4 = (tid & 7) * 4;
    int t0 = tok[r], t1 = tok[r + 32], t2 = tok[r + 64], t3 = tok[r + 96];
    float4 ar[4], br[4];
    ar[0] = *(const float4*)(g_xc + (size_t)t0 * DM + c4);
    ar[1] = *(const float4*)(g_xc + (size_t)t1 * DM + c4);
    ar[2] = *(const float4*)(g_xc + (size_t)t2 * DM + c4);
    ar[3] = *(const float4*)(g_xc + (size_t)t3 * DM + c4);
    #pragma unroll
    for (int i = 0; i < 4; i++)
        br[i] = *(const float4*)(Bb + (size_t)(r + i * 32) * DM + c4);
    #pragma unroll
    for (int i = 0; i < 4; i++) {
        st_raw(As, (r + i * 32) * 36 + c4, ar[i]);
        st_raw(Bs, (r + i * 32) * 36 + c4, br[i]);
    }
    __syncthreads();
    int stage = 0;
    for (int kk = 0; kk < DM; kk += 32) {
        if (kk + 32 < DM) {
            ar[0] = *(const float4*)(g_xc + (size_t)t0 * DM + kk + 32 + c4);
            ar[1] = *(const float4*)(g_xc + (size_t)t1 * DM + kk + 32 + c4);
            ar[2] = *(const float4*)(g_xc + (size_t)t2 * DM + kk + 32 + c4);
            ar[3] = *(const float4*)(g_xc + (size_t)t3 * DM + kk + 32 + c4);
            #pragma unroll
            for (int i = 0; i < 4; i++)
                br[i] = *(const float4*)(Bb + (size_t)(r + i * 32) * DM + kk + 32 + c4);
        }
        mma_tile(As + stage * STG, Bs + stage * STG, acc, lane, warpM, warpN);
        if (kk + 32 < DM) {
            int ns = stage ^ 1;
            #pragma unroll
            for (int i = 0; i < 4; i++) {
                st_raw(As + ns * STG, (r + i * 32) * 36 + c4, ar[i]);
                st_raw(Bs + ns * STG, (r + i * 32) * 36 + c4, br[i]);
            }
        }
        __syncthreads();
        stage ^= 1;
    }
    int lr = lane >> 2, lc = (lane & 3) * 2;
    #pragma unroll
    for (int mf = 0; mf < 4; mf++)
        #pragma unroll
        for (int h = 0; h < 2; h++) {
            int rl = warpM * 64 + mf * 16 + lr + h * 8;
            if (rl < rows) {
                float* cp = g_gu + (size_t)(r0 + rl) * (2 * HF) + n0;
                #pragma unroll
                for (int nf = 0; nf < 4; nf++) {
                    int col = warpN * 32 + nf * 8 + lc;
                    *(float2*)(cp + col) =
                        make_float2(acc[mf][nf][h * 2], acc[mf][nf][h * 2 + 1]);
                }
            }
        }
}

// ---------------- silu: act = tf32(silu(gate)*up) ----------------
__global__ void silu_kernel() {
    size_t i = (size_t)blockIdx.x * blockDim.x + threadIdx.x;
    size_t rr = i >> 9;
    size_t h4 = i & 511;
    const float4* gu4 = (const float4*)g_gu;
    float4 gv = gu4[rr * 1024 + h4];
    float4 uv = gu4[rr * 1024 + 512 + h4];
    float4 o;
    o.x = tf32r(gv.x / (1.f + expf(-gv.x)) * uv.x);
    o.y = tf32r(gv.y / (1.f + expf(-gv.y)) * uv.y);
    o.z = tf32r(gv.z / (1.f + expf(-gv.z)) * uv.z);
    o.w = tf32r(gv.w / (1.f + expf(-gv.w)) * uv.w);
    ((float4*)g_act)[rr * 512 + h4] = o;
}

// ---------------- expert pass B ----------------
__global__ void __launch_bounds__(256) expB_tc(const float* __restrict__ x)
{
    int t = blockIdx.x;
    if (t >= g_ntiles) return;
    int e = g_tile_e[t], r0 = g_tile_r0[t], rows = g_tile_rows[t];
    int n0 = blockIdx.y * 128;
    extern __shared__ unsigned sm[];
    unsigned* As = sm;
    unsigned* Bs = sm + 2 * STG;
    __shared__ int s_asn[128];
    int tid = threadIdx.x, lane = tid & 31, warp = tid >> 5;
    int warpM = warp >> 2, warpN = warp & 3;
    if (tid < 128) s_asn[tid] = (tid < rows) ? g_idx_list[r0 + tid] : 0;
    float acc[4][4][4] = {};
    const float* Ab = g_act + (size_t)r0 * HF;
    const float* Bb = g_w2c + (size_t)e * DM * HF + (size_t)n0 * HF;
    int r = tid >> 3, c4 = (tid & 7) * 4;
    float4 ar[4], br[4];
    #pragma unroll
    for (int i = 0; i < 4; i++) {
        ar[i] = *(const float4*)(Ab + (size_t)(r + i * 32) * HF + c4);
        br[i] = *(const float4*)(Bb + (size_t)(r + i * 32) * HF + c4);
    }
    #pragma unroll
    for (int i = 0; i < 4; i++) {
        st_raw(As, (r + i * 32) * 36 + c4, ar[i]);
        st_raw(Bs, (r + i * 32) * 36 + c4, br[i]);
    }
    __syncthreads();
    int stage = 0;
    for (int kk = 0; kk < HF; kk += 32) {
        if (kk + 32 < HF) {
            #pragma unroll
            for (int i = 0; i < 4; i++) {
                ar[i] = *(const float4*)(Ab + (size_t)(r + i * 32) * HF + kk + 32 + c4);
                br[i] = *(const float4*)(Bb + (size_t)(r + i * 32) * HF + kk + 32 + c4);
            }
        }
        mma_tile(As + stage * STG, Bs + stage * STG, acc, lane, warpM, warpN);
        if (kk + 32 < HF) {
            int ns = stage ^ 1;
            #pragma unroll
            for (int i = 0; i < 4; i++) {
                st_raw(As + ns * STG, (r + i * 32) * 36 + c4, ar[i]);
                st_raw(Bs + ns * STG, (r + i * 32) * 36 + c4, br[i]);
            }
        }
        __syncthreads();
        stage ^= 1;
    }
    int lr = lane >> 2, lc = (lane & 3) * 2;
    #pragma unroll
    for (int mf = 0; mf < 4; mf++)
        #pragma unroll
        for (int h = 0; h < 2; h++) {
            int rl = warpM * 64 + mf * 16 + lr + h * 8;
            if (rl < rows) {
                int asn = s_asn[rl];
                int n = asn >> 1, slot = asn & 1;
                float kp = g_keep[asn];
                const float* xr = x + (size_t)n * DM + n0;
                float* tr = g_tokens + ((size_t)n * 3 + slot) * DM + n0;
                #pragma unroll
                for (int nf = 0; nf < 4; nf++) {
                    int col = warpN * 32 + nf * 8 + lc;
                    tr[col]     = kp * (xr[col]     + acc[mf][nf][h * 2]);
                    tr[col + 1] = kp * (xr[col + 1] + acc[mf][nf][h * 2 + 1]);
                }
            }
        }
}

// ---------------- small kernels ----------------
__global__ void zero_accum_kernel() {
    int t = threadIdx.x;
    if (t < NE) { g_router_sum[t] = 0.f; g_assign_sum[t] = 0.f; g_counts[t] = 0; g_fill[t] = 0; }
    if (t == 0) { g_z2 = 0.f; g_keepcnt = 0; }
}

__global__ void med_init_kernel(const float* __restrict__ mediator) {
    size_t total = (size_t)NTOK * DM;
    for (size_t i = blockIdx.x * blockDim.x + threadIdx.x; i < total; i += (size_t)gridDim.x * blockDim.x) {
        size_t n = i / DM;
        size_t d = i - n * DM;
        g_tokens[(n * 3 + 2) * DM + d] = mediator[d];
    }
}

// warp-per-token gate: 8 tokens/block, block-aggregated stats
__global__ void __launch_bounds__(256) gate_kernel(const float* __restrict__ x,
                                                   const float* __restrict__ gw,
                                                   float* __restrict__ out) {
    __shared__ float wsh[NE * DM];
    __shared__ float s_rs[NE], s_as[NE], s_z2s;
    __shared__ int   s_c[NE];
    int tid = threadIdx.x;
    for (int i = tid; i < NE * DM; i += 256) wsh[i] = gw[i];
    if (tid < NE) { s_rs[tid] = 0.f; s_as[tid] = 0.f; s_c[tid] = 0; }
    if (tid == 0) s_z2s = 0.f;
    __syncthreads();
    int warp = tid >> 5, lane = tid & 31;
    int n = blockIdx.x * 8 + warp;
    const float* xr = x + (size_t)n * DM;
    float xv[24];
    #pragma unroll
    for (int i = 0; i < 24; i++) xv[i] = xr[lane + i * 32];
    float l[NE];
    #pragma unroll
    for (int e = 0; e < NE; e++) {
        float s = 0.f;
        const float* w = wsh + e * DM;
        #pragma unroll
        for (int i = 0; i < 24; i++) s += xv[i] * w[lane + i * 32];
        #pragma unroll
        for (int o = 16; o; o >>= 1) s += __shfl_xor_sync(0xffffffffu, s, o);
        l[e] = s;
    }
    if (lane == 0) {
        int i1 = 0; float v1 = l[0];
        #pragma unroll
        for (int e = 1; e < NE; e++) if (l[e] > v1) { v1 = l[e]; i1 = e; }
        int i2 = -1; float v2 = -3.4e38f;
        #pragma unroll
        for (int e = 0; e < NE; e++) if (e != i1 && l[e] > v2) { v2 = l[e]; i2 = e; }
        float e2 = expf(v2 - v1);
        float inv = 1.f / (1.f + e2);
        float p1 = inv, p2 = e2 * inv;
        float se = 0.f;
        #pragma unroll
        for (int e = 0; e < NE; e++) se += expf(l[e] - v1);
        float z = v1 + logf(se);
        #pragma unroll
        for (int e = 0; e < NE; e++) atomicAdd(&s_rs[e], expf(l[e] - v1) / se);
        atomicAdd(&s_as[i1], p1);
        atomicAdd(&s_as[i2], p2);
        atomicAdd(&s_z2s, z * z);
        atomicAdd(&s_c[i1], 1);
        atomicAdd(&s_c[i2], 1);
        g_te[2 * n] = i1; g_te[2 * n + 1] = i2;
        g_prio[2 * n] = v1; g_prio[2 * n + 1] = v2;
        g_tpk[2 * n] = p1; g_tpk[2 * n + 1] = p2;
        out[(size_t)NTOK * DM + 1 + 2 * n]     = (float)i1;
        out[(size_t)NTOK * DM + 1 + 2 * n + 1] = (float)i2;
    }
    __syncthreads();
    if (tid < NE) {
        atomicAdd(&g_router_sum[tid], s_rs[tid]);
        atomicAdd(&g_assign_sum[tid], s_as[tid]);
        atomicAdd(&g_counts[tid], s_c[tid]);
    }
    if (tid == 0) atomicAdd(&g_z2, s_z2s);
}

__global__ void build_tiles_kernel() {
    if (threadIdx.x != 0 || blockIdx.x != 0) return;
    int off = 0, nt = 0;
    for (int e = 0; e < NE; e++) {
        g_offsets[e] = off;
        int c = g_counts[e];
        int ntile = (c + 127) >> 7;
        for (int t = 0; t < ntile; t++) {
            g_tile_e[nt] = e;
            g_tile_r0[nt] = off + t * 128;
            int r = c - t * 128;
            g_tile_rows[nt] = r < 128 ? r : 128;
            nt++;
        }
        off += c;
    }
    g_ntiles = nt;
}

__global__ void scatter_kernel() {
    int i = blockIdx.x * 256 + threadIdx.x;
    if (i >= NKA) return;
    int e = g_te[i];
    int p = atomicAdd(&g_fill[e], 1);
    g_idx_list[g_offsets[e] + p] = i;
}

__global__ void keep_kernel() {
    int i = blockIdx.x * 256 + threadIdx.x;
    if (i >= NKA) return;
    int e = g_te[i];
    int kp;
    if (g_counts[e] <= CAPC) {
        kp = 1;
    } else {
        float pi = g_prio[i];
        int rank = 0;
        for (int j = 0; j < NKA; j++) {
            if (g_te[j] == e) {
                float pj = g_prio[j];
                if (pj > pi || (pj == pi && j < i)) rank++;
            }
        }
        kp = (rank < CAPC) ? 1 : 0;
    }
    g_keep[i] = (float)kp;
    atomicAdd(&g_keepcnt, kp);
}

__global__ void attn_kernel() {
    int n = blockIdx.x;
    int h = threadIdx.x >> 5, lane = threadIdx.x & 31;
    const float* base = g_qkv + (size_t)n * 3 * QKVW;
    float q[3][6], k[3][6], v[3][6];
    #pragma unroll
    for (int li = 0; li < 3; li++) {
        const float* bp = base + (size_t)li * QKVW + h * 192 + lane * 6;
        #pragma unroll
        for (int dd = 0; dd < 6; dd++) {
            q[li][dd] = bp[dd];
            k[li][dd] = bp[dd + DM];
            v[li][dd] = bp[dd + 2 * DM];
        }
    }
    const float scale = 0.07216878364870322f;
    float b0 = (g_keep[2 * n]     > 0.5f) ? 0.f : -1e9f;
    float b1 = (g_keep[2 * n + 1] > 0.5f) ? 0.f : -1e9f;
    float s[3][3];
    #pragma unroll
    for (int qi = 0; qi < 3; qi++) {
        #pragma unroll
        for (int kj = 0; kj < 3; kj++) {
            float t = 0.f;
            #pragma unroll
            for (int dd = 0; dd < 6; dd++) t += q[qi][dd] * k[kj][dd];
            #pragma unroll
            for (int o = 16; o; o >>= 1) t += __shfl_xor_sync(0xffffffffu, t, o);
            s[qi][kj] = t * scale;
        }
        s[qi][0] += b0;
        s[qi][1] += b1;
    }
    #pragma unroll
    for (int qi = 0; qi < 3; qi++) {
        float m = fmaxf(s[qi][0], fmaxf(s[qi][1], s[qi][2]));
        float e0 = expf(s[qi][0] - m), e1 = expf(s[qi][1] - m), e2 = expf(s[qi][2] - m);
        float inv = 1.f / (e0 + e1 + e2);
        float a0 = e0 * inv, a1 = e1 * inv, a2 = e2 * inv;
        float* op = g_attn + (size_t)(n * 3 + qi) * DM + h * 192 + lane * 6;
        #pragma unroll
        for (int dd = 0; dd < 6; dd++)
            op[dd] = tf32r(a0 * v[0][dd] + a1 * v[1][dd] + a2 * v[2][dd]);
    }
}

__global__ void rms_dual_kernel(const float* __restrict__ w1, const float* __restrict__ w2) {
    __shared__ float sh[8];
    __shared__ float sscale;
    int m = blockIdx.x, tid = threadIdx.x;
    float* row = g_tokens + (size_t)m * DM;
    float v0 = row[tid], v1 = row[tid + 256], v2 = row[tid + 512];
    float ss = v0 * v0 + v1 * v1 + v2 * v2;
    #pragma unroll
    for (int o = 16; o; o >>= 1) ss += __shfl_xor_sync(0xffffffffu, ss, o);
    if ((tid & 31) == 0) sh[tid >> 5] = ss;
    __syncthreads();
    if (tid == 0) {
        float t = 0.f;
        #pragma unroll
        for (int i = 0; i < 8; i++) t += sh[i];
        sscale = rsqrtf(t * (1.f / DM) + 1e-6f);
    }
    __syncthreads();
    float s1 = sscale;
    float t0 = v0 * s1 * w1[tid];
    float t1 = v1 * s1 * w1[tid + 256];
    float t2 = v2 * s1 * w1[tid + 512];
    row[tid] = t0; row[tid + 256] = t1; row[tid + 512] = t2;
    float ss2 = t0 * t0 + t1 * t1 + t2 * t2;
    #pragma unroll
    for (int o = 16; o; o >>= 1) ss2 += __shfl_xor_sync(0xffffffffu, ss2, o);
    __syncthreads();
    if ((tid & 31) == 0) sh[tid >> 5] = ss2;
    __syncthreads();
    if (tid == 0) {
        float t = 0.f;
        #pragma unroll
        for (int i = 0; i < 8; i++) t += sh[i];
        sscale = rsqrtf(t * (1.f / DM) + 1e-6f);
    }
    __syncthreads();
    float s2 = sscale;
    float* ur = g_u + (size_t)m * DM;
    ur[tid]       = tf32r(t0 * s2 * w2[tid]);
    ur[tid + 256] = tf32r(t1 * s2 * w2[tid + 256]);
    ur[tid + 512] = tf32r(t2 * s2 * w2[tid + 512]);
}

__global__ void fuse_prep_kernel(const float* __restrict__ fgw, const float* __restrict__ fgb) {
    __shared__ float sh[8];
    __shared__ float par[3];
    int n = blockIdx.x, tid = threadIdx.x;
    const float* med = g_tokens + ((size_t)n * 3 + 2) * DM;
    float s = med[tid] * fgw[tid] + med[tid + 256] * fgw[tid + 256] + med[tid + 512] * fgw[tid + 512];
    #pragma unroll
    for (int o = 16; o; o >>= 1) s += __shfl_xor_sync(0xffffffffu, s, o);
    if ((tid & 31) == 0) sh[tid >> 5] = s;
    __syncthreads();
    if (tid == 0) {
        float t = 0.f;
        #pragma unroll
        for (int i = 0; i < 8; i++) t += sh[i];
        float g = 1.f / (1.f + expf(-(t + fgb[0])));
        float tp0 = g_tpk[2 * n] * g_keep[2 * n];
        float tp1 = g_tpk[2 * n + 1] * g_keep[2 * n + 1];
        float den = tp0 + tp1;
        par[0] = g;
        par[1] = den > 0.f ? tp0 / den : 0.f;
        par[2] = den > 0.f ? tp1 / den : 0.f;
    }
    __syncthreads();
    float g = par[0], w0 = par[1], w1 = par[2];
    const float* e0 = g_tokens + ((size_t)n * 3 + 0) * DM;
    const float* e1 = g_tokens + ((size_t)n * 3 + 1) * DM;
    float* fm = g_fm + (size_t)n * DM;
    #pragma unroll
    for (int c = 0; c < 3; c++) {
        int d = tid + c * 256;
        fm[d] = tf32r(g * med[d] + (1.f - g) * (w0 * e0[d] + w1 * e1[d]));
    }
}

__global__ void aux_kernel(float* __restrict__ out) {
    if (threadIdx.x != 0 || blockIdx.x != 0) return;
    float bal = 0.f;
    for (int e = 0; e < NE; e++)
        bal += (g_router_sum[e] / (float)NTOK) * (g_assign_sum[e] / (float)NTOK);
    bal *= (float)NE;
    float aux = 0.01f * bal + 0.001f * (g_z2 / (float)NTOK)
              + 0.001f * (1.f - (float)g_keepcnt / (float)NKA);
    out[(size_t)NTOK * DM] = aux;
}

// ---------------- launch ----------------
extern "C" void kernel_launch(void* const* d_in, const int* in_sizes, int n_in,
                              void* d_out, int out_size) {
    const float* x          = (const float*)d_in[0];
    const float* gate_w     = (const float*)d_in[1];
    const float* w13        = (const float*)d_in[2];
    const float* w2         = (const float*)d_in[3];
    const float* in_proj_w  = (const float*)d_in[4];
    const float* in_proj_b  = (const float*)d_in[5];
    const float* out_w      = (const float*)d_in[6];
    const float* out_b      = (const float*)d_in[7];
    const float* norm1_w    = (const float*)d_in[8];
    const float* norm2_w    = (const float*)d_in[9];
    const float* ffn_w1     = (const float*)d_in[10];
    const float* ffn_w2     = (const float*)d_in[11];
    const float* mediator   = (const float*)d_in[12];
    const float* fuse_gate_w= (const float*)d_in[13];
    const float* fuse_gate_b= (const float*)d_in[14];
    const float* o_proj_w   = (const float*)d_in[15];
    float* out = (float*)d_out;

    float *p_tokens, *p_qkv, *p_attn, *p_u, *p_h, *p_fm;
    float *p_xc, *p_w13c, *p_w2c, *p_ipwc, *p_owc, *p_f1c, *p_f2c, *p_opc;
    cudaGetSymbolAddress((void**)&p_tokens, g_tokens);
    cudaGetSymbolAddress((void**)&p_qkv, g_qkv);
    cudaGetSymbolAddress((void**)&p_attn, g_attn);
    cudaGetSymbolAddress((void**)&p_u, g_u);
    cudaGetSymbolAddress((void**)&p_h, g_hbuf);
    cudaGetSymbolAddress((void**)&p_fm, g_fm);
    cudaGetSymbolAddress((void**)&p_xc, g_xc);
    cudaGetSymbolAddress((void**)&p_w13c, g_w13c);
    cudaGetSymbolAddress((void**)&p_w2c, g_w2c);
    cudaGetSymbolAddress((void**)&p_ipwc, g_ipwc);
    cudaGetSymbolAddress((void**)&p_owc, g_owc);
    cudaGetSymbolAddress((void**)&p_f1c, g_f1c);
    cudaGetSymbolAddress((void**)&p_f2c, g_f2c);
    cudaGetSymbolAddress((void**)&p_opc, g_opc);

    const int SMEMB = 4 * 4 * STG;  // 73728 bytes
    static int attr_done = 0;
    cudaFuncSetAttribute(gemm_tc<false, true,  false>, cudaFuncAttributeMaxDynamicSharedMemorySize, SMEMB);
    cudaFuncSetAttribute(gemm_tc<false, false, false>, cudaFuncAttributeMaxDynamicSharedMemorySize, SMEMB);
    cudaFuncSetAttribute(gemm_tc<true,  false, true >, cudaFuncAttributeMaxDynamicSharedMemorySize, SMEMB);
    cudaFuncSetAttribute(expA_tc, cudaFuncAttributeMaxDynamicSharedMemorySize, SMEMB);
    cudaFuncSetAttribute(expB_tc, cudaFuncAttributeMaxDynamicSharedMemorySize, SMEMB);
    (void)attr_done;

    zero_accum_kernel<<<1, 32>>>();
    gate_kernel<<<NTOK / 8, 256>>>(x, gate_w, out);

    // pre-round weights + x
    cvt_kernel<<<(NE * 2 * HF * DM / 4 + 255) / 256, 256>>>(w13, p_w13c, NE * 2 * HF * DM / 4, 1.f);
    cvt_kernel<<<(NE * DM * HF / 4 + 255) / 256, 256>>>(w2, p_w2c, NE * DM * HF / 4, 1.f);
    cvt_kernel<<<(NTOK * DM / 4 + 255) / 256, 256>>>(x, p_xc, NTOK * DM / 4, 2.f);
    cvt_kernel<<<(QKVW * DM / 4 + 255) / 256, 256>>>(in_proj_w, p_ipwc, QKVW * DM / 4, 1.f);
    cvt_kernel<<<(DM * DM / 4 + 255) / 256, 256>>>(out_w, p_owc, DM * DM / 4, 1.f);
    cvt_kernel<<<(DM * DM / 4 + 255) / 256, 256>>>(ffn_w1, p_f1c, DM * DM / 4, 1.f);
    cvt_kernel<<<(DM * DM / 4 + 255) / 256, 256>>>(ffn_w2, p_f2c, DM * DM / 4, 1.f);
    cvt_kernel<<<(DM * DM / 4 + 255) / 256, 256>>>(o_proj_w, p_opc, DM * DM / 4, 1.f);

    build_tiles_kernel<<<1, 1>>>();
    scatter_kernel<<<NKA / 256, 256>>>();
    keep_kernel<<<NKA / 256, 256>>>();
    med_init_kernel<<<2048, 256>>>(mediator);

    expA_tc<<<dim3(136, 2 * HF / 128), 256, SMEMB>>>();
    silu_kernel<<<32768, 256>>>();
    expB_tc<<<dim3(136, DM / 128), 256, SMEMB>>>(x);

    for (int step = 0; step < 2; step++) {
        gemm_tc<false, true, false><<<dim3(MROW / 128, QKVW / 128), 256, SMEMB>>>(
            p_tokens, p_ipwc, in_proj_b, nullptr, p_qkv, QKVW, DM);
        attn_kernel<<<NTOK, 128>>>();
        gemm_tc<false, false, false><<<dim3(MROW / 128, DM / 128), 256, SMEMB>>>(
            p_attn, p_owc, out_b, p_tokens, p_tokens, DM, DM);
        rms_dual_kernel<<<MROW, 256>>>(norm1_w, norm2_w);
        gemm_tc<true, false, true><<<dim3(MROW / 128, DM / 128), 256, SMEMB>>>(
            p_u, p_f1c, nullptr, nullptr, p_h, DM, DM);
        gemm_tc<false, false, false><<<dim3(MROW / 128, DM / 128), 256, SMEMB>>>(
            p_h, p_f2c, nullptr, p_tokens, p_tokens, DM, DM);
    }

    fuse_prep_kernel<<<NTOK, 256>>>(fuse_gate_w, fuse_gate_b);
    gemm_tc<false, false, false><<<dim3(NTOK / 128, DM / 128), 256, SMEMB>>>(
        p_fm, p_opc, nullptr, nullptr, out, DM, DM);
    aux_kernel<<<1, 1>>>(out);
}

// round 5
// speedup vs baseline: 5.9438x; 1.6106x over previous
#include <cuda_runtime.h>
#include <cuda_fp16.h>
#include <math.h>
#include <stdint.h>

#define NTOK 8192
#define DM   768
#define NE   8
#define NKA  16384
#define HF   2048
#define CAPC 4096
#define MROW 24576
#define QKVW 2304
#define MAXT 136

// ---------------- scratch ----------------
__device__ float g_router_sum[NE];
__device__ float g_assign_sum[NE];
__device__ float g_z2;
__device__ int   g_counts[NE];
__device__ int   g_fill[NE];
__device__ int   g_offsets[NE];
__device__ int   g_keepcnt;
__device__ int   g_te[NKA];
__device__ float g_prio[NKA];
__device__ float g_tpk[NKA];
__device__ float g_keep[NKA];
__device__ int   g_idx_list[NKA];
__device__ int   g_tile_e[MAXT];
__device__ int   g_tile_r0[MAXT];
__device__ int   g_tile_rows[MAXT];
__device__ int   g_ntiles;

__device__ float  g_tokens[(size_t)MROW * DM];          // fp32 residual stream
__device__ __half g_guh[(size_t)NKA * 2 * HF];
__device__ __half g_acth[(size_t)(NKA + 128) * HF];
__device__ __half g_qkvh[(size_t)MROW * QKVW];
__device__ __half g_attnh[(size_t)MROW * DM];
__device__ __half g_uh[(size_t)MROW * DM];
__device__ __half g_hh[(size_t)MROW * DM];
__device__ __half g_fmh[(size_t)NTOK * DM];

// fp16 copies of weights / inputs
__device__ __half g_xh[(size_t)NTOK * DM];              // 2*x
__device__ __half g_w13h[(size_t)NE * 2 * HF * DM];
__device__ __half g_w2h[(size_t)NE * DM * HF];
__device__ __half g_ipwh[(size_t)QKVW * DM];
__device__ __half g_owh[(size_t)DM * DM];
__device__ __half g_f1h[(size_t)DM * DM];
__device__ __half g_f2h[(size_t)DM * DM];
__device__ __half g_oph[(size_t)DM * DM];

// ---------------- helpers ----------------
__device__ __forceinline__ uint32_t h2u(float a, float b) {
    __half2 h = __floats2half2_rn(a, b);
    return *(uint32_t*)&h;
}

__device__ __forceinline__ void mma16(float* c, const uint32_t* a, const uint32_t* b) {
    asm volatile(
        "mma.sync.aligned.m16n8k16.row.col.f32.f16.f16.f32 "
        "{%0,%1,%2,%3},{%4,%5,%6,%7},{%8,%9},{%0,%1,%2,%3};"
        : "+f"(c[0]), "+f"(c[1]), "+f"(c[2]), "+f"(c[3])
        : "r"(a[0]), "r"(a[1]), "r"(a[2]), "r"(a[3]), "r"(b[0]), "r"(b[1]));
}

// one 128x128x32 tile: 8 warps, warp tile 64x32, 2 k-steps of 16
__device__ __forceinline__ void mma_tile_h(const __half* As, const __half* Bs,
                                           float acc[4][4][4], int lane, int warpM, int warpN) {
    int lr = lane >> 2, lq = (lane & 3) * 2;
    #pragma unroll
    for (int ks = 0; ks < 2; ks++) {
        int kb = ks * 16;
        uint32_t a[4][4], b[4][2];
        #pragma unroll
        for (int mf = 0; mf < 4; mf++) {
            int rb = warpM * 64 + mf * 16 + lr;
            a[mf][0] = *(const uint32_t*)(As + rb * 40 + kb + lq);
            a[mf][1] = *(const uint32_t*)(As + (rb + 8) * 40 + kb + lq);
            a[mf][2] = *(const uint32_t*)(As + rb * 40 + kb + 8 + lq);
            a[mf][3] = *(const uint32_t*)(As + (rb + 8) * 40 + kb + 8 + lq);
        }
        #pragma unroll
        for (int nf = 0; nf < 4; nf++) {
            int cb = warpN * 32 + nf * 8 + lr;
            b[nf][0] = *(const uint32_t*)(Bs + cb * 40 + kb + lq);
            b[nf][1] = *(const uint32_t*)(Bs + cb * 40 + kb + 8 + lq);
        }
        #pragma unroll
        for (int mf = 0; mf < 4; mf++)
            #pragma unroll
            for (int nf = 0; nf < 4; nf++)
                mma16(acc[mf][nf], a[mf], b[nf]);
    }
}

// ---------------- generic NT GEMM (fp16 in, fp32 acc) ----------------
template<bool CVTA, bool BIAS, bool RES, bool GELU, bool HOUT>
__global__ void __launch_bounds__(256) gemm_h(
    const void* __restrict__ Av, const __half* __restrict__ B,
    const float* __restrict__ bias, const float* __restrict__ res,
    void* __restrict__ Cv, int N, int K)
{
    __shared__ __half As[2][128 * 40];
    __shared__ __half Bs[2][128 * 40];
    int tid = threadIdx.x, lane = tid & 31, warp = tid >> 5;
    int warpM = warp >> 2, warpN = warp & 3;
    size_t m0 = (size_t)blockIdx.x * 128;
    int n0 = blockIdx.y * 128;
    const float*  Af = (const float*)Av;
    const __half* Ah = (const __half*)Av;
    const __half* Bb = B + (size_t)n0 * K;
    float acc[4][4][4] = {};

    // stage 0 direct load
    if (CVTA) {
        #pragma unroll
        for (int i = 0; i < 4; i++) {
            int c = tid + i * 256;
            int row = c >> 3, c4 = (c & 7) * 4;
            float4 v = *(const float4*)(Af + (m0 + row) * K + c4);
            *(uint2*)&As[0][row * 40 + c4] = make_uint2(h2u(v.x, v.y), h2u(v.z, v.w));
        }
    } else {
        #pragma unroll
        for (int i = 0; i < 2; i++) {
            int c = tid + i * 256;
            int row = c >> 2, c8 = (c & 3) * 8;
            *(uint4*)&As[0][row * 40 + c8] = *(const uint4*)(Ah + (m0 + row) * K + c8);
        }
    }
    #pragma unroll
    for (int i = 0; i < 2; i++) {
        int c = tid + i * 256;
        int row = c >> 2, c8 = (c & 3) * 8;
        *(uint4*)&Bs[0][row * 40 + c8] = *(const uint4*)(Bb + (size_t)row * K + c8);
    }
    __syncthreads();

    int s = 0;
    for (int kk = 0; kk < K; kk += 32) {
        float4 af[4];
        uint4  ah[2], bh[2];
        if (kk + 32 < K) {
            if (CVTA) {
                #pragma unroll
                for (int i = 0; i < 4; i++) {
                    int c = tid + i * 256;
                    int row = c >> 3, c4 = (c & 7) * 4;
                    af[i] = *(const float4*)(Af + (m0 + row) * K + kk + 32 + c4);
                }
            } else {
                #pragma unroll
                for (int i = 0; i < 2; i++) {
                    int c = tid + i * 256;
                    int row = c >> 2, c8 = (c & 3) * 8;
                    ah[i] = *(const uint4*)(Ah + (m0 + row) * K + kk + 32 + c8);
                }
            }
            #pragma unroll
            for (int i = 0; i < 2; i++) {
                int c = tid + i * 256;
                int row = c >> 2, c8 = (c & 3) * 8;
                bh[i] = *(const uint4*)(Bb + (size_t)row * K + kk + 32 + c8);
            }
        }
        mma_tile_h(As[s], Bs[s], acc, lane, warpM, warpN);
        if (kk + 32 < K) {
            int ns = s ^ 1;
            if (CVTA) {
                #pragma unroll
                for (int i = 0; i < 4; i++) {
                    int c = tid + i * 256;
                    int row = c >> 3, c4 = (c & 7) * 4;
                    *(uint2*)&As[ns][row * 40 + c4] =
                        make_uint2(h2u(af[i].x, af[i].y), h2u(af[i].z, af[i].w));
                }
            } else {
                #pragma unroll
                for (int i = 0; i < 2; i++) {
                    int c = tid + i * 256;
                    int row = c >> 2, c8 = (c & 3) * 8;
                    *(uint4*)&As[ns][row * 40 + c8] = ah[i];
                }
            }
            #pragma unroll
            for (int i = 0; i < 2; i++) {
                int c = tid + i * 256;
                int row = c >> 2, c8 = (c & 3) * 8;
                *(uint4*)&Bs[ns][row * 40 + c8] = bh[i];
            }
        }
        __syncthreads();
        s ^= 1;
    }

    int lr = lane >> 2, lc = (lane & 3) * 2;
    #pragma unroll
    for (int mf = 0; mf < 4; mf++)
        #pragma unroll
        for (int h = 0; h < 2; h++) {
            size_t m = m0 + warpM * 64 + mf * 16 + lr + h * 8;
            #pragma unroll
            for (int nf = 0; nf < 4; nf++) {
                int col = n0 + warpN * 32 + nf * 8 + lc;
                float v0 = acc[mf][nf][h * 2], v1 = acc[mf][nf][h * 2 + 1];
                if (BIAS) { v0 += bias[col]; v1 += bias[col + 1]; }
                if (RES)  { v0 += res[m * N + col]; v1 += res[m * N + col + 1]; }
                if (GELU) {
                    v0 = 0.5f * v0 * (1.f + erff(v0 * 0.70710678118654752f));
                    v1 = 0.5f * v1 * (1.f + erff(v1 * 0.70710678118654752f));
                }
                if (HOUT) {
                    __half2 hv = __floats2half2_rn(v0, v1);
                    *(__half2*)((__half*)Cv + m * N + col) = hv;
                } else {
                    *(float2*)((float*)Cv + m * N + col) = make_float2(v0, v1);
                }
            }
        }
}

// ---------------- expert pass A: gu = (2x)@w13^T, gathered rows ----------------
__global__ void __launch_bounds__(256) expA_h()
{
    int t = blockIdx.x;
    if (t >= g_ntiles) return;
    __shared__ __half As[2][128 * 40];
    __shared__ __half Bs[2][128 * 40];
    __shared__ int tok[128];
    int tid = threadIdx.x, lane = tid & 31, warp = tid >> 5;
    int warpM = warp >> 2, warpN = warp & 3;
    int e = g_tile_e[t], r0 = g_tile_r0[t], rows = g_tile_rows[t];
    int n0 = blockIdx.y * 128;
    if (tid < 128) tok[tid] = (tid < rows) ? (g_idx_list[r0 + tid] >> 1) : 0;
    __syncthreads();
    const __half* Bb = g_w13h + (size_t)e * 2 * HF * DM + (size_t)n0 * DM;
    float acc[4][4][4] = {};

    #pragma unroll
    for (int i = 0; i < 2; i++) {
        int c = tid + i * 256;
        int row = c >> 2, c8 = (c & 3) * 8;
        *(uint4*)&As[0][row * 40 + c8] = *(const uint4*)(g_xh + (size_t)tok[row] * DM + c8);
        *(uint4*)&Bs[0][row * 40 + c8] = *(const uint4*)(Bb + (size_t)row * DM + c8);
    }
    __syncthreads();

    int s = 0;
    for (int kk = 0; kk < DM; kk += 32) {
        uint4 ah[2], bh[2];
        if (kk + 32 < DM) {
            #pragma unroll
            for (int i = 0; i < 2; i++) {
                int c = tid + i * 256;
                int row = c >> 2, c8 = (c & 3) * 8;
                ah[i] = *(const uint4*)(g_xh + (size_t)tok[row] * DM + kk + 32 + c8);
                bh[i] = *(const uint4*)(Bb + (size_t)row * DM + kk + 32 + c8);
            }
        }
        mma_tile_h(As[s], Bs[s], acc, lane, warpM, warpN);
        if (kk + 32 < DM) {
            int ns = s ^ 1;
            #pragma unroll
            for (int i = 0; i < 2; i++) {
                int c = tid + i * 256;
                int row = c >> 2, c8 = (c & 3) * 8;
                *(uint4*)&As[ns][row * 40 + c8] = ah[i];
                *(uint4*)&Bs[ns][row * 40 + c8] = bh[i];
            }
        }
        __syncthreads();
        s ^= 1;
    }

    int lr = lane >> 2, lc = (lane & 3) * 2;
    #pragma unroll
    for (int mf = 0; mf < 4; mf++)
        #pragma unroll
        for (int h = 0; h < 2; h++) {
            int rl = warpM * 64 + mf * 16 + lr + h * 8;
            if (rl < rows) {
                __half* cp = g_guh + (size_t)(r0 + rl) * (2 * HF) + n0;
                #pragma unroll
                for (int nf = 0; nf < 4; nf++) {
                    int col = warpN * 32 + nf * 8 + lc;
                    *(__half2*)(cp + col) =
                        __floats2half2_rn(acc[mf][nf][h * 2], acc[mf][nf][h * 2 + 1]);
                }
            }
        }
}

// ---------------- silu ----------------
__global__ void silu_kernel() {
    size_t i = (size_t)blockIdx.x * blockDim.x + threadIdx.x;   // over NKA*HF/4
    size_t rr = i >> 9;             // HF/4 = 512 uint2-groups per row
    size_t h4 = i & 511;
    const uint2* gu = (const uint2*)g_guh;
    uint2 gv = gu[rr * 1024 + h4];
    uint2 uv = gu[rr * 1024 + 512 + h4];
    float2 g0 = __half22float2(*(__half2*)&gv.x);
    float2 g1 = __half22float2(*(__half2*)&gv.y);
    float2 u0 = __half22float2(*(__half2*)&uv.x);
    float2 u1 = __half22float2(*(__half2*)&uv.y);
    uint2 o;
    __half2 o0 = __floats2half2_rn(g0.x / (1.f + expf(-g0.x)) * u0.x,
                                   g0.y / (1.f + expf(-g0.y)) * u0.y);
    __half2 o1 = __floats2half2_rn(g1.x / (1.f + expf(-g1.x)) * u1.x,
                                   g1.y / (1.f + expf(-g1.y)) * u1.y);
    o.x = *(uint32_t*)&o0; o.y = *(uint32_t*)&o1;
    ((uint2*)g_acth)[rr * 512 + h4] = o;
}

// ---------------- expert pass B ----------------
__global__ void __launch_bounds__(256) expB_h(const float* __restrict__ x)
{
    int t = blockIdx.x;
    if (t >= g_ntiles) return;
    __shared__ __half As[2][128 * 40];
    __shared__ __half Bs[2][128 * 40];
    __shared__ int s_asn[128];
    int tid = threadIdx.x, lane = tid & 31, warp = tid >> 5;
    int warpM = warp >> 2, warpN = warp & 3;
    int e = g_tile_e[t], r0 = g_tile_r0[t], rows = g_tile_rows[t];
    int n0 = blockIdx.y * 128;
    if (tid < 128) s_asn[tid] = (tid < rows) ? g_idx_list[r0 + tid] : 0;
    const __half* Ab = g_acth + (size_t)r0 * HF;
    const __half* Bb = g_w2h + (size_t)e * DM * HF + (size_t)n0 * HF;
    float acc[4][4][4] = {};

    #pragma unroll
    for (int i = 0; i < 2; i++) {
        int c = tid + i * 256;
        int row = c >> 2, c8 = (c & 3) * 8;
        *(uint4*)&As[0][row * 40 + c8] = *(const uint4*)(Ab + (size_t)row * HF + c8);
        *(uint4*)&Bs[0][row * 40 + c8] = *(const uint4*)(Bb + (size_t)row * HF + c8);
    }
    __syncthreads();

    int s = 0;
    for (int kk = 0; kk < HF; kk += 32) {
        uint4 ah[2], bh[2];
        if (kk + 32 < HF) {
            #pragma unroll
            for (int i = 0; i < 2; i++) {
                int c = tid + i * 256;
                int row = c >> 2, c8 = (c & 3) * 8;
                ah[i] = *(const uint4*)(Ab + (size_t)row * HF + kk + 32 + c8);
                bh[i] = *(const uint4*)(Bb + (size_t)row * HF + kk + 32 + c8);
            }
        }
        mma_tile_h(As[s], Bs[s], acc, lane, warpM, warpN);
        if (kk + 32 < HF) {
            int ns = s ^ 1;
            #pragma unroll
            for (int i = 0; i < 2; i++) {
                int c = tid + i * 256;
                int row = c >> 2, c8 = (c & 3) * 8;
                *(uint4*)&As[ns][row * 40 + c8] = ah[i];
                *(uint4*)&Bs[ns][row * 40 + c8] = bh[i];
            }
        }
        __syncthreads();
        s ^= 1;
    }

    int lr = lane >> 2, lc = (lane & 3) * 2;
    #pragma unroll
    for (int mf = 0; mf < 4; mf++)
        #pragma unroll
        for (int h = 0; h < 2; h++) {
            int rl = warpM * 64 + mf * 16 + lr + h * 8;
            if (rl < rows) {
                int a = s_asn[rl];
                int n = a >> 1, slot = a & 1;
                float kp = g_keep[a];
                const float* xr = x + (size_t)n * DM + n0;
                float* tr = g_tokens + ((size_t)n * 3 + slot) * DM + n0;
                #pragma unroll
                for (int nf = 0; nf < 4; nf++) {
                    int col = warpN * 32 + nf * 8 + lc;
                    tr[col]     = kp * (xr[col]     + acc[mf][nf][h * 2]);
                    tr[col + 1] = kp * (xr[col + 1] + acc[mf][nf][h * 2 + 1]);
                }
            }
        }
}

// ---------------- cvt fp32 -> fp16 ----------------
__global__ void cvth_kernel(const float* __restrict__ sIn, __half* __restrict__ d,
                            int n4, float alpha) {
    int i = blockIdx.x * 256 + threadIdx.x;
    if (i >= n4) return;
    float4 v = ((const float4*)sIn)[i];
    ((uint2*)d)[i] = make_uint2(h2u(alpha * v.x, alpha * v.y), h2u(alpha * v.z, alpha * v.w));
}

// ---------------- small kernels ----------------
__global__ void zero_accum_kernel() {
    int t = threadIdx.x;
    if (t < NE) { g_router_sum[t] = 0.f; g_assign_sum[t] = 0.f; g_counts[t] = 0; g_fill[t] = 0; }
    if (t == 0) { g_z2 = 0.f; g_keepcnt = 0; }
}

__global__ void med_init_kernel(const float* __restrict__ mediator) {
    size_t total = (size_t)NTOK * DM;
    for (size_t i = blockIdx.x * blockDim.x + threadIdx.x; i < total; i += (size_t)gridDim.x * blockDim.x) {
        size_t n = i / DM;
        size_t d = i - n * DM;
        g_tokens[(n * 3 + 2) * DM + d] = mediator[d];
    }
}

__global__ void __launch_bounds__(256) gate_kernel(const float* __restrict__ x,
                                                   const float* __restrict__ gw,
                                                   float* __restrict__ out) {
    __shared__ float wsh[NE * DM];
    __shared__ float s_rs[NE], s_as[NE], s_z2s;
    __shared__ int   s_c[NE];
    int tid = threadIdx.x;
    for (int i = tid; i < NE * DM; i += 256) wsh[i] = gw[i];
    if (tid < NE) { s_rs[tid] = 0.f; s_as[tid] = 0.f; s_c[tid] = 0; }
    if (tid == 0) s_z2s = 0.f;
    __syncthreads();
    int warp = tid >> 5, lane = tid & 31;
    int n = blockIdx.x * 8 + warp;
    const float* xr = x + (size_t)n * DM;
    float xv[24];
    #pragma unroll
    for (int i = 0; i < 24; i++) xv[i] = xr[lane + i * 32];
    float l[NE];
    #pragma unroll
    for (int e = 0; e < NE; e++) {
        float sv = 0.f;
        const float* w = wsh + e * DM;
        #pragma unroll
        for (int i = 0; i < 24; i++) sv += xv[i] * w[lane + i * 32];
        #pragma unroll
        for (int o = 16; o; o >>= 1) sv += __shfl_xor_sync(0xffffffffu, sv, o);
        l[e] = sv;
    }
    if (lane == 0) {
        int i1 = 0; float v1 = l[0];
        #pragma unroll
        for (int e = 1; e < NE; e++) if (l[e] > v1) { v1 = l[e]; i1 = e; }
        int i2 = -1; float v2 = -3.4e38f;
        #pragma unroll
        for (int e = 0; e < NE; e++) if (e != i1 && l[e] > v2) { v2 = l[e]; i2 = e; }
        float e2 = expf(v2 - v1);
        float inv = 1.f / (1.f + e2);
        float p1 = inv, p2 = e2 * inv;
        float se = 0.f;
        #pragma unroll
        for (int e = 0; e < NE; e++) se += expf(l[e] - v1);
        float z = v1 + logf(se);
        #pragma unroll
        for (int e = 0; e < NE; e++) atomicAdd(&s_rs[e], expf(l[e] - v1) / se);
        atomicAdd(&s_as[i1], p1);
        atomicAdd(&s_as[i2], p2);
        atomicAdd(&s_z2s, z * z);
        atomicAdd(&s_c[i1], 1);
        atomicAdd(&s_c[i2], 1);
        g_te[2 * n] = i1; g_te[2 * n + 1] = i2;
        g_prio[2 * n] = v1; g_prio[2 * n + 1] = v2;
        g_tpk[2 * n] = p1; g_tpk[2 * n + 1] = p2;
        out[(size_t)NTOK * DM + 1 + 2 * n]     = (float)i1;
        out[(size_t)NTOK * DM + 1 + 2 * n + 1] = (float)i2;
    }
    __syncthreads();
    if (tid < NE) {
        atomicAdd(&g_router_sum[tid], s_rs[tid]);
        atomicAdd(&g_assign_sum[tid], s_as[tid]);
        atomicAdd(&g_counts[tid], s_c[tid]);
    }
    if (tid == 0) atomicAdd(&g_z2, s_z2s);
}

__global__ void build_tiles_kernel() {
    if (threadIdx.x != 0 || blockIdx.x != 0) return;
    int off = 0, nt = 0;
    for (int e = 0; e < NE; e++) {
        g_offsets[e] = off;
        int c = g_counts[e];
        int ntile = (c + 127) >> 7;
        for (int t = 0; t < ntile; t++) {
            g_tile_e[nt] = e;
            g_tile_r0[nt] = off + t * 128;
            int r = c - t * 128;
            g_tile_rows[nt] = r < 128 ? r : 128;
            nt++;
        }
        off += c;
    }
    g_ntiles = nt;
}

__global__ void scatter_kernel() {
    int i = blockIdx.x * 256 + threadIdx.x;
    if (i >= NKA) return;
    int e = g_te[i];
    int p = atomicAdd(&g_fill[e], 1);
    g_idx_list[g_offsets[e] + p] = i;
}

__global__ void keep_kernel() {
    int i = blockIdx.x * 256 + threadIdx.x;
    if (i >= NKA) return;
    int e = g_te[i];
    int kp;
    if (g_counts[e] <= CAPC) {
        kp = 1;
    } else {
        float pi = g_prio[i];
        int rank = 0;
        for (int j = 0; j < NKA; j++) {
            if (g_te[j] == e) {
                float pj = g_prio[j];
                if (pj > pi || (pj == pi && j < i)) rank++;
            }
        }
        kp = (rank < CAPC) ? 1 : 0;
    }
    g_keep[i] = (float)kp;
    atomicAdd(&g_keepcnt, kp);
}

__global__ void attn_kernel() {
    int n = blockIdx.x;
    int h = threadIdx.x >> 5, lane = threadIdx.x & 31;
    const __half* base = g_qkvh + (size_t)n * 3 * QKVW;
    float q[3][6], k[3][6], v[3][6];
    #pragma unroll
    for (int li = 0; li < 3; li++) {
        const __half* bp = base + (size_t)li * QKVW + h * 192 + lane * 6;
        #pragma unroll
        for (int dd = 0; dd < 6; dd++) {
            q[li][dd] = __half2float(bp[dd]);
            k[li][dd] = __half2float(bp[dd + DM]);
            v[li][dd] = __half2float(bp[dd + 2 * DM]);
        }
    }
    const float scale = 0.07216878364870322f;
    float b0 = (g_keep[2 * n]     > 0.5f) ? 0.f : -1e9f;
    float b1 = (g_keep[2 * n + 1] > 0.5f) ? 0.f : -1e9f;
    float s[3][3];
    #pragma unroll
    for (int qi = 0; qi < 3; qi++) {
        #pragma unroll
        for (int kj = 0; kj < 3; kj++) {
            float t = 0.f;
            #pragma unroll
            for (int dd = 0; dd < 6; dd++) t += q[qi][dd] * k[kj][dd];
            #pragma unroll
            for (int o = 16; o; o >>= 1) t += __shfl_xor_sync(0xffffffffu, t, o);
            s[qi][kj] = t * scale;
        }
        s[qi][0] += b0;
        s[qi][1] += b1;
    }
    #pragma unroll
    for (int qi = 0; qi < 3; qi++) {
        float m = fmaxf(s[qi][0], fmaxf(s[qi][1], s[qi][2]));
        float e0 = expf(s[qi][0] - m), e1 = expf(s[qi][1] - m), e2 = expf(s[qi][2] - m);
        float inv = 1.f / (e0 + e1 + e2);
        float a0 = e0 * inv, a1 = e1 * inv, a2 = e2 * inv;
        __half* op = g_attnh + (size_t)(n * 3 + qi) * DM + h * 192 + lane * 6;
        #pragma unroll
        for (int dd = 0; dd < 6; dd++)
            op[dd] = __float2half_rn(a0 * v[0][dd] + a1 * v[1][dd] + a2 * v[2][dd]);
    }
}

__global__ void rms_dual_kernel(const float* __restrict__ w1, const float* __restrict__ w2) {
    __shared__ float sh[8];
    __shared__ float sscale;
    int m = blockIdx.x, tid = threadIdx.x;
    float* row = g_tokens + (size_t)m * DM;
    float v0 = row[tid], v1 = row[tid + 256], v2 = row[tid + 512];
    float ss = v0 * v0 + v1 * v1 + v2 * v2;
    #pragma unroll
    for (int o = 16; o; o >>= 1) ss += __shfl_xor_sync(0xffffffffu, ss, o);
    if ((tid & 31) == 0) sh[tid >> 5] = ss;
    __syncthreads();
    if (tid == 0) {
        float t = 0.f;
        #pragma unroll
        for (int i = 0; i < 8; i++) t += sh[i];
        sscale = rsqrtf(t * (1.f / DM) + 1e-6f);
    }
    __syncthreads();
    float s1 = sscale;
    float t0 = v0 * s1 * w1[tid];
    float t1 = v1 * s1 * w1[tid + 256];
    float t2 = v2 * s1 * w1[tid + 512];
    row[tid] = t0; row[tid + 256] = t1; row[tid + 512] = t2;
    float ss2 = t0 * t0 + t1 * t1 + t2 * t2;
    #pragma unroll
    for (int o = 16; o; o >>= 1) ss2 += __shfl_xor_sync(0xffffffffu, ss2, o);
    __syncthreads();
    if ((tid & 31) == 0) sh[tid >> 5] = ss2;
    __syncthreads();
    if (tid == 0) {
        float t = 0.f;
        #pragma unroll
        for (int i = 0; i < 8; i++) t += sh[i];
        sscale = rsqrtf(t * (1.f / DM) + 1e-6f);
    }
    __syncthreads();
    float s2 = sscale;
    __half* ur = g_uh + (size_t)m * DM;
    ur[tid]       = __float2half_rn(t0 * s2 * w2[tid]);
    ur[tid + 256] = __float2half_rn(t1 * s2 * w2[tid + 256]);
    ur[tid + 512] = __float2half_rn(t2 * s2 * w2[tid + 512]);
}

__global__ void fuse_prep_kernel(const float* __restrict__ fgw, const float* __restrict__ fgb) {
    __shared__ float sh[8];
    __shared__ float par[3];
    int n = blockIdx.x, tid = threadIdx.x;
    const float* med = g_tokens + ((size_t)n * 3 + 2) * DM;
    float s = med[tid] * fgw[tid] + med[tid + 256] * fgw[tid + 256] + med[tid + 512] * fgw[tid + 512];
    #pragma unroll
    for (int o = 16; o; o >>= 1) s += __shfl_xor_sync(0xffffffffu, s, o);
    if ((tid & 31) == 0) sh[tid >> 5] = s;
    __syncthreads();
    if (tid == 0) {
        float t = 0.f;
        #pragma unroll
        for (int i = 0; i < 8; i++) t += sh[i];
        float g = 1.f / (1.f + expf(-(t + fgb[0])));
        float tp0 = g_tpk[2 * n] * g_keep[2 * n];
        float tp1 = g_tpk[2 * n + 1] * g_keep[2 * n + 1];
        float den = tp0 + tp1;
        par[0] = g;
        par[1] = den > 0.f ? tp0 / den : 0.f;
        par[2] = den > 0.f ? tp1 / den : 0.f;
    }
    __syncthreads();
    float g = par[0], w0 = par[1], w1 = par[2];
    const float* e0 = g_tokens + ((size_t)n * 3 + 0) * DM;
    const float* e1 = g_tokens + ((size_t)n * 3 + 1) * DM;
    __half* fm = g_fmh + (size_t)n * DM;
    #pragma unroll
    for (int c = 0; c < 3; c++) {
        int d = tid + c * 256;
        fm[d] = __float2half_rn(g * med[d] + (1.f - g) * (w0 * e0[d] + w1 * e1[d]));
    }
}

__global__ void aux_kernel(float* __restrict__ out) {
    if (threadIdx.x != 0 || blockIdx.x != 0) return;
    float bal = 0.f;
    for (int e = 0; e < NE; e++)
        bal += (g_router_sum[e] / (float)NTOK) * (g_assign_sum[e] / (float)NTOK);
    bal *= (float)NE;
    float aux = 0.01f * bal + 0.001f * (g_z2 / (float)NTOK)
              + 0.001f * (1.f - (float)g_keepcnt / (float)NKA);
    out[(size_t)NTOK * DM] = aux;
}

// ---------------- launch ----------------
extern "C" void kernel_launch(void* const* d_in, const int* in_sizes, int n_in,
                              void* d_out, int out_size) {
    const float* x          = (const float*)d_in[0];
    const float* gate_w     = (const float*)d_in[1];
    const float* w13        = (const float*)d_in[2];
    const float* w2         = (const float*)d_in[3];
    const float* in_proj_w  = (const float*)d_in[4];
    const float* in_proj_b  = (const float*)d_in[5];
    const float* out_w      = (const float*)d_in[6];
    const float* out_b      = (const float*)d_in[7];
    const float* norm1_w    = (const float*)d_in[8];
    const float* norm2_w    = (const float*)d_in[9];
    const float* ffn_w1     = (const float*)d_in[10];
    const float* ffn_w2     = (const float*)d_in[11];
    const float* mediator   = (const float*)d_in[12];
    const float* fuse_gate_w= (const float*)d_in[13];
    const float* fuse_gate_b= (const float*)d_in[14];
    const float* o_proj_w   = (const float*)d_in[15];
    float* out = (float*)d_out;

    float* p_tokens;
    __half *p_xh, *p_w13h, *p_w2h, *p_ipwh, *p_owh, *p_f1h, *p_f2h, *p_oph;
    __half *p_qkvh, *p_attnh, *p_uh, *p_hh, *p_fmh;
    cudaGetSymbolAddress((void**)&p_tokens, g_tokens);
    cudaGetSymbolAddress((void**)&p_xh, g_xh);
    cudaGetSymbolAddress((void**)&p_w13h, g_w13h);
    cudaGetSymbolAddress((void**)&p_w2h, g_w2h);
    cudaGetSymbolAddress((void**)&p_ipwh, g_ipwh);
    cudaGetSymbolAddress((void**)&p_owh, g_owh);
    cudaGetSymbolAddress((void**)&p_f1h, g_f1h);
    cudaGetSymbolAddress((void**)&p_f2h, g_f2h);
    cudaGetSymbolAddress((void**)&p_oph, g_oph);
    cudaGetSymbolAddress((void**)&p_qkvh, g_qkvh);
    cudaGetSymbolAddress((void**)&p_attnh, g_attnh);
    cudaGetSymbolAddress((void**)&p_uh, g_uh);
    cudaGetSymbolAddress((void**)&p_hh, g_hh);
    cudaGetSymbolAddress((void**)&p_fmh, g_fmh);

    zero_accum_kernel<<<1, 32>>>();
    gate_kernel<<<NTOK / 8, 256>>>(x, gate_w, out);

    cvth_kernel<<<(int)(((size_t)NE * 2 * HF * DM / 4 + 255) / 256), 256>>>(w13, p_w13h, NE * 2 * HF * DM / 4, 1.f);
    cvth_kernel<<<(NE * DM * HF / 4 + 255) / 256, 256>>>(w2, p_w2h, NE * DM * HF / 4, 1.f);
    cvth_kernel<<<(NTOK * DM / 4 + 255) / 256, 256>>>(x, p_xh, NTOK * DM / 4, 2.f);
    cvth_kernel<<<(QKVW * DM / 4 + 255) / 256, 256>>>(in_proj_w, p_ipwh, QKVW * DM / 4, 1.f);
    cvth_kernel<<<(DM * DM / 4 + 255) / 256, 256>>>(out_w, p_owh, DM * DM / 4, 1.f);
    cvth_kernel<<<(DM * DM / 4 + 255) / 256, 256>>>(ffn_w1, p_f1h, DM * DM / 4, 1.f);
    cvth_kernel<<<(DM * DM / 4 + 255) / 256, 256>>>(ffn_w2, p_f2h, DM * DM / 4, 1.f);
    cvth_kernel<<<(DM * DM / 4 + 255) / 256, 256>>>(o_proj_w, p_oph, DM * DM / 4, 1.f);

    build_tiles_kernel<<<1, 1>>>();
    scatter_kernel<<<NKA / 256, 256>>>();
    keep_kernel<<<NKA / 256, 256>>>();
    med_init_kernel<<<2048, 256>>>(mediator);

    expA_h<<<dim3(MAXT, 2 * HF / 128), 256>>>();
    silu_kernel<<<NKA * (HF / 4) / 256 / 4, 1024>>>();
    expB_h<<<dim3(MAXT, DM / 128), 256>>>(x);

    for (int step = 0; step < 2; step++) {
        gemm_h<true, true, false, false, true><<<dim3(MROW / 128, QKVW / 128), 256>>>(
            p_tokens, p_ipwh, in_proj_b, nullptr, p_qkvh, QKVW, DM);
        attn_kernel<<<NTOK, 128>>>();
        gemm_h<false, true, true, false, false><<<dim3(MROW / 128, DM / 128), 256>>>(
            p_attnh, p_owh, out_b, p_tokens, p_tokens, DM, DM);
        rms_dual_kernel<<<MROW, 256>>>(norm1_w, norm2_w);
        gemm_h<false, false, false, true, true><<<dim3(MROW / 128, DM / 128), 256>>>(
            p_uh, p_f1h, nullptr, nullptr, p_hh, DM, DM);
        gemm_h<false, false, true, false, false><<<dim3(MROW / 128, DM / 128), 256>>>(
            p_hh, p_f2h, nullptr, p_tokens, p_tokens, DM, DM);
    }

    fuse_prep_kernel<<<NTOK, 256>>>(fuse_gate_w, fuse_gate_b);
    gemm_h<false, false, false, false, false><<<dim3(NTOK / 128, DM / 128), 256>>>(
        p_fmh, p_oph, nullptr, nullptr, out, DM, DM);
    aux_kernel<<<1, 1>>>(out);
}